// round 11
// baseline (speedup 1.0000x reference)
#include <cuda_runtime.h>
#include <cuda_bf16.h>
#include <cuda_fp16.h>
#include <math.h>
#include <stdint.h>

#define B_ 32
#define S_ 1024
#define D_ 512
#define H_ 8
#define L_ 3
#define FF_ 2048
#define C_ 6
#define BS_ (B_*S_)

// ---------------- scratch (device globals) ----------------------------------
static __device__ float          g_x[(size_t)BS_*D_];        // residual fp32
static __device__ __nv_bfloat16  g_xb[(size_t)BS_*D_];       // residual bf16
static __device__ __nv_bfloat16  g_qkvb[(size_t)BS_*3*D_];   // qkv: Q(bf16,scaled) K(bf16) V(f16 bits)
static __device__ __nv_bfloat16  g_ob[(size_t)BS_*D_];       // attn out bf16
static __device__ float          g_p[(size_t)BS_*D_];        // proj out fp32
static __device__ float          g_pool[B_*D_];
static __device__ float          g_h1[B_*FF_];
#define WQKV_OFF(l) ((size_t)(l) * (size_t)(D_*3*D_))
#define WFC_OFF(l)  ((size_t)3 * (D_*3*D_) + (size_t)(l) * (D_*D_))
#define WTOT ((size_t)3 * (D_*3*D_) + (size_t)3 * (D_*D_))
static __device__ uint16_t       g_wh[WTOT];
static __device__ uint16_t       g_wl[WTOT];

// ---------------- asm helpers ------------------------------------------------
__device__ __forceinline__ uint32_t s2u(const void* p) {
    return (uint32_t)__cvta_generic_to_shared(p);
}
#define LDSM4(R, addr) \
    asm volatile("ldmatrix.sync.aligned.m8n8.x4.shared.b16 {%0,%1,%2,%3}, [%4];" \
        : "=r"((R)[0]), "=r"((R)[1]), "=r"((R)[2]), "=r"((R)[3]) : "r"(addr))
#define LDSM4T(R, addr) \
    asm volatile("ldmatrix.sync.aligned.m8n8.x4.trans.shared.b16 {%0,%1,%2,%3}, [%4];" \
        : "=r"((R)[0]), "=r"((R)[1]), "=r"((R)[2]), "=r"((R)[3]) : "r"(addr))
#define MMA_BF16(c, a, b) \
    asm volatile("mma.sync.aligned.m16n8k16.row.col.f32.bf16.bf16.f32 " \
        "{%0,%1,%2,%3},{%4,%5,%6,%7},{%8,%9},{%0,%1,%2,%3};" \
        : "+f"((c)[0]), "+f"((c)[1]), "+f"((c)[2]), "+f"((c)[3]) \
        : "r"((a)[0]), "r"((a)[1]), "r"((a)[2]), "r"((a)[3]), "r"((b)[0]), "r"((b)[1]))
#define MMA_F16(c, a, b) \
    asm volatile("mma.sync.aligned.m16n8k16.row.col.f32.f16.f16.f32 " \
        "{%0,%1,%2,%3},{%4,%5,%6,%7},{%8,%9},{%0,%1,%2,%3};" \
        : "+f"((c)[0]), "+f"((c)[1]), "+f"((c)[2]), "+f"((c)[3]) \
        : "r"((a)[0]), "r"((a)[1]), "r"((a)[2]), "r"((a)[3]), "r"((b)[0]), "r"((b)[1]))
#define CP16(dst, src) \
    asm volatile("cp.async.cg.shared.global [%0], [%1], 16;" :: "r"(dst), "l"(src))
#define CP_COMMIT asm volatile("cp.async.commit_group;")
#define CP_WAIT(n) asm volatile("cp.async.wait_group %0;" :: "n"(n))
// pack (lo,hi) fp32 pair -> f16x2, then 2^x elementwise
__device__ __forceinline__ uint32_t exp2_f16x2(float lo, float hi) {
    uint32_t d;
    asm("{.reg .b32 t;\n\t"
        "cvt.rn.f16x2.f32 t, %1, %2;\n\t"
        "ex2.approx.f16x2 %0, t;}"
        : "=r"(d) : "f"(hi), "f"(lo));
    return d;
}

// ---------------- fp32 -> bf16 hi/lo split (weights) -------------------------
__global__ void __launch_bounds__(256) convert_hl(const float* __restrict__ in,
                                                  uint16_t* __restrict__ hi,
                                                  uint16_t* __restrict__ lo) {
    int i = blockIdx.x * 256 + threadIdx.x;
    float4 v = ((const float4*)in)[i];
    float f[4] = {v.x, v.y, v.z, v.w};
    ushort4 ph, pl;
    unsigned short* hh = (unsigned short*)&ph;
    unsigned short* ll = (unsigned short*)&pl;
    #pragma unroll
    for (int j = 0; j < 4; j++) {
        __nv_bfloat16 h = __float2bfloat16(f[j]);
        float hf = __bfloat162float(h);
        __nv_bfloat16 l = __float2bfloat16(f[j] - hf);
        hh[j] = *(unsigned short*)&h;
        ll[j] = *(unsigned short*)&l;
    }
    ((ushort4*)hi)[i] = ph;
    ((ushort4*)lo)[i] = pl;
}

// ---------------- pipelined bf16x2 GEMM, 256x128 CTA tile --------------------
// C = A(bf16)[M,K] @ (Wh+Wl)[K,N] + bias. 3-stage cp.async, 1 CTA/SM,
// warp tile 128x32 (8 warps, 2x4). M multiple of 256, N of 128, K of 32.
// qkvmode: Q cols (col%192<64) bf16*log2e/8, K cols bf16, V cols f16.
#define AST 40
#define BST 136
#define A_EL (256*AST)
#define B_EL (32*BST)
#define GSMEM ((3*A_EL + 6*B_EL) * 2)   // 113664 bytes
__global__ void __launch_bounds__(256, 1) gemm_bf16x2(
    const __nv_bfloat16* __restrict__ A,
    const uint16_t* __restrict__ Bh, const uint16_t* __restrict__ Bl,
    const float* __restrict__ bias,
    float* __restrict__ Cf, __nv_bfloat16* __restrict__ Cb, int N, int K,
    int qkvmode) {
    extern __shared__ __align__(16) uint16_t sm_[];
    uint16_t* sA  = sm_;                  // 3 x 256 x AST
    uint16_t* sBh = sm_ + 3 * A_EL;       // 3 x 32 x BST
    uint16_t* sBl = sBh + 3 * B_EL;
    const int tid = threadIdx.x;
    const int lane = tid & 31, warp = tid >> 5;
    const int wr = warp >> 2, wc = warp & 3;          // 2 x 4 warp grid
    const size_t aRow0 = (size_t)blockIdx.y * 256;
    const int bCol0 = blockIdx.x * 128;
    const int lrow = lane & 15, lseg = lane >> 4;

    float acc[32][4];                                  // mi 0..7, ni 0..3
    #pragma unroll
    for (int i = 0; i < 32; i++)
        #pragma unroll
        for (int j = 0; j < 4; j++) acc[i][j] = 0.f;

    const int nk = K / 32;
    auto load_stage = [&](int st, int kt) {
        #pragma unroll
        for (int i = 0; i < 4; i++) {                  // A: 1024 chunks
            int c = tid + i * 256;
            int r = c >> 2, seg = c & 3;
            CP16(s2u(&sA[st * A_EL + r * AST + seg * 8]),
                 A + (aRow0 + r) * K + kt + seg * 8);
        }
        #pragma unroll
        for (int i = 0; i < 2; i++) {                  // Bh/Bl: 512 chunks each
            int c = tid + i * 256;
            int r = c >> 4, seg = c & 15;
            CP16(s2u(&sBh[st * B_EL + r * BST + seg * 8]),
                 Bh + (size_t)(kt + r) * N + bCol0 + seg * 8);
            CP16(s2u(&sBl[st * B_EL + r * BST + seg * 8]),
                 Bl + (size_t)(kt + r) * N + bCol0 + seg * 8);
        }
    };
    load_stage(0, 0); CP_COMMIT;
    load_stage(1, 32); CP_COMMIT;

    int stC = 0, stL = 2;
    for (int it = 0; it < nk; it++) {
        if (it == nk - 1) { CP_WAIT(0); } else { CP_WAIT(1); }
        __syncthreads();
        if (it + 2 < nk) { load_stage(stL, (it + 2) * 32); CP_COMMIT; }
        if (++stL == 3) stL = 0;
        #pragma unroll
        for (int k16 = 0; k16 < 32; k16 += 16) {
            uint32_t a[8][4], bh[4][2], bl[4][2];
            #pragma unroll
            for (int mi = 0; mi < 8; mi++)
                LDSM4(a[mi], s2u(&sA[stC * A_EL + (wr * 128 + mi * 16 + lrow) * AST + k16 + lseg * 8]));
            #pragma unroll
            for (int np = 0; np < 2; np++) {
                uint32_t t4[4];
                LDSM4T(t4, s2u(&sBh[stC * B_EL + (k16 + lrow) * BST + wc * 32 + np * 16 + lseg * 8]));
                bh[np*2][0] = t4[0]; bh[np*2][1] = t4[1];
                bh[np*2+1][0] = t4[2]; bh[np*2+1][1] = t4[3];
                LDSM4T(t4, s2u(&sBl[stC * B_EL + (k16 + lrow) * BST + wc * 32 + np * 16 + lseg * 8]));
                bl[np*2][0] = t4[0]; bl[np*2][1] = t4[1];
                bl[np*2+1][0] = t4[2]; bl[np*2+1][1] = t4[3];
            }
            #pragma unroll
            for (int mi = 0; mi < 8; mi++)
                #pragma unroll
                for (int ni = 0; ni < 4; ni++)
                    MMA_BF16(acc[mi * 4 + ni], a[mi], bh[ni]);
            #pragma unroll
            for (int mi = 0; mi < 8; mi++)
                #pragma unroll
                for (int ni = 0; ni < 4; ni++)
                    MMA_BF16(acc[mi * 4 + ni], a[mi], bl[ni]);
        }
        if (++stC == 3) stC = 0;
    }
    #pragma unroll
    for (int mi = 0; mi < 8; mi++) {
        size_t row = aRow0 + wr * 128 + mi * 16 + (lane >> 2);
        #pragma unroll
        for (int ni = 0; ni < 4; ni++) {
            int col = bCol0 + wc * 32 + ni * 8 + (lane & 3) * 2;
            float b0 = 0.f, b1 = 0.f;
            if (bias) { b0 = bias[col]; b1 = bias[col + 1]; }
            float* c = acc[mi * 4 + ni];
            float v00 = c[0] + b0, v01 = c[1] + b1;
            float v10 = c[2] + b0, v11 = c[3] + b1;
            if (Cf) {
                *(float2*)&Cf[row * N + col] = make_float2(v00, v01);
                *(float2*)&Cf[(row + 8) * N + col] = make_float2(v10, v11);
            }
            if (Cb) {
                uint32_t w0, w1;
                int cm = col % 192;
                if (qkvmode && cm >= 128) {           // V: f16
                    __half2 h0 = __floats2half2_rn(v00, v01);
                    __half2 h1 = __floats2half2_rn(v10, v11);
                    w0 = *(uint32_t*)&h0; w1 = *(uint32_t*)&h1;
                } else {
                    float sc = (qkvmode && cm < 64) ? 0.1803368801f : 1.0f;
                    __nv_bfloat162 t0 = __floats2bfloat162_rn(v00 * sc, v01 * sc);
                    __nv_bfloat162 t1 = __floats2bfloat162_rn(v10 * sc, v11 * sc);
                    w0 = *(uint32_t*)&t0; w1 = *(uint32_t*)&t1;
                }
                *(uint32_t*)&Cb[row * N + col] = w0;
                *(uint32_t*)&Cb[(row + 8) * N + col] = w1;
            }
        }
    }
}

// ---------------- fused flash attention (f16 exp + mma row-sums) -------------
#define KST 72
#define FSMEM ((128*KST + 3*64*KST*2) * 2)   // 73728 bytes
__global__ void __launch_bounds__(256) flash_kernel(
    const __nv_bfloat16* __restrict__ qkvb, __nv_bfloat16* __restrict__ ob) {
    extern __shared__ __align__(16) __nv_bfloat16 fsm_[];
    __nv_bfloat16* sQ = fsm_;
    __nv_bfloat16* sK = fsm_ + 128 * KST;
    __nv_bfloat16* sV = sK + 3 * 64 * KST;
    const int bh = blockIdx.y;
    const int b = bh >> 3, h = bh & 7;
    const int q0 = blockIdx.x * 128;
    const int tid = threadIdx.x, lane = tid & 31, warp = tid >> 5;
    const __nv_bfloat16* qb = qkvb + (size_t)(b * S_) * 1536 + h * 192;
    const __nv_bfloat16* kb = qb + 64;
    const __nv_bfloat16* vb = qb + 128;

    auto load_kv = [&](int buf, int t) {
        #pragma unroll
        for (int i = 0; i < 2; i++) {
            int c = tid + i * 256;
            int r = c >> 3, seg = c & 7;
            CP16(s2u(&sK[buf * 64 * KST + r * KST + seg * 8]),
                 kb + (size_t)(t * 64 + r) * 1536 + seg * 8);
            CP16(s2u(&sV[buf * 64 * KST + r * KST + seg * 8]),
                 vb + (size_t)(t * 64 + r) * 1536 + seg * 8);
        }
    };
    #pragma unroll
    for (int i = 0; i < 4; i++) {
        int c = tid + i * 256;
        int r = c >> 3, seg = c & 7;
        CP16(s2u(&sQ[r * KST + seg * 8]), qb + (size_t)(q0 + r) * 1536 + seg * 8);
    }
    load_kv(0, 0); CP_COMMIT;
    load_kv(1, 1); CP_COMMIT;
    CP_WAIT(1);
    __syncthreads();

    uint32_t qf[4][4];
    const int qr = warp * 16;
    #pragma unroll
    for (int kk = 0; kk < 4; kk++)
        LDSM4(qf[kk], s2u(&sQ[(qr + (lane & 15)) * KST + kk * 16 + (lane >> 4) * 8]));

    float o[8][4];
    #pragma unroll
    for (int i = 0; i < 8; i++)
        #pragma unroll
        for (int j = 0; j < 4; j++) o[i][j] = 0.f;
    float lacc[4] = {0.f, 0.f, 0.f, 0.f};   // P @ ones : row sums in fp32
    const uint32_t onesb[2] = {0x3C003C00u, 0x3C003C00u};

    const int kRow = ((lane >> 4) & 1) * 8 + (lane & 7);
    const int kCol = ((lane >> 3) & 1) * 8;
    const int vRow = ((lane >> 3) & 1) * 8 + (lane & 7);
    const int vCol = ((lane >> 4) & 1) * 8;

    int stC = 0, stL = 2;
    for (int t = 0; t < 16; t++) {
        if (t == 15) { CP_WAIT(0); } else { CP_WAIT(1); }
        __syncthreads();
        if (t + 2 < 16) { load_kv(stL, t + 2); CP_COMMIT; }
        if (++stL == 3) stL = 0;
        const int kbuf = stC * 64 * KST;
        if (++stC == 3) stC = 0;

        float s[8][4];
        #pragma unroll
        for (int i = 0; i < 8; i++)
            #pragma unroll
            for (int j = 0; j < 4; j++) s[i][j] = 0.f;
        #pragma unroll
        for (int kk = 0; kk < 4; kk++) {
            uint32_t kf[8][2];
            #pragma unroll
            for (int nf2 = 0; nf2 < 4; nf2++) {
                uint32_t t4[4];
                LDSM4(t4, s2u(&sK[kbuf + (nf2 * 16 + kRow) * KST + kk * 16 + kCol]));
                kf[nf2*2][0] = t4[0]; kf[nf2*2][1] = t4[1];
                kf[nf2*2+1][0] = t4[2]; kf[nf2*2+1][1] = t4[3];
            }
            #pragma unroll
            for (int nf = 0; nf < 8; nf++)
                MMA_BF16(s[nf], qf[kk], kf[nf]);
        }

        uint32_t pa[4][4];
        #pragma unroll
        for (int kk = 0; kk < 4; kk++) {
            pa[kk][0] = exp2_f16x2(s[2*kk][0],   s[2*kk][1]);
            pa[kk][1] = exp2_f16x2(s[2*kk][2],   s[2*kk][3]);
            pa[kk][2] = exp2_f16x2(s[2*kk+1][0], s[2*kk+1][1]);
            pa[kk][3] = exp2_f16x2(s[2*kk+1][2], s[2*kk+1][3]);
            MMA_F16(lacc, pa[kk], onesb);
        }

        #pragma unroll
        for (int kk = 0; kk < 4; kk++) {
            uint32_t vf[8][2];
            #pragma unroll
            for (int nf2 = 0; nf2 < 4; nf2++) {
                uint32_t t4[4];
                LDSM4T(t4, s2u(&sV[kbuf + (kk * 16 + vRow) * KST + nf2 * 16 + vCol]));
                vf[nf2*2][0] = t4[0]; vf[nf2*2][1] = t4[1];
                vf[nf2*2+1][0] = t4[2]; vf[nf2*2+1][1] = t4[3];
            }
            #pragma unroll
            for (int nf = 0; nf < 8; nf++)
                MMA_F16(o[nf], pa[kk], vf[nf]);
        }
    }

    float inv0 = 1.f / lacc[0], inv1 = 1.f / lacc[2];
    size_t r0 = (size_t)b * S_ + q0 + qr + (lane >> 2);
    size_t r1 = r0 + 8;
    #pragma unroll
    for (int nf = 0; nf < 8; nf++) {
        int col = h * 64 + nf * 8 + (lane & 3) * 2;
        *(__nv_bfloat162*)&ob[r0 * D_ + col] =
            __floats2bfloat162_rn(o[nf][0] * inv0, o[nf][1] * inv0);
        *(__nv_bfloat162*)&ob[r1 * D_ + col] =
            __floats2bfloat162_rn(o[nf][2] * inv1, o[nf][3] * inv1);
    }
}

// ---------------- embedding + sinusoidal PE ----------------------------------
__global__ void __launch_bounds__(256) embed_kernel(const int* __restrict__ tokens,
                                                    const float* __restrict__ emb) {
    int idx = blockIdx.x * 256 + threadIdx.x;
    int d = idx & (D_ - 1);
    int bs = idx >> 9;
    int s = bs & (S_ - 1);
    int tok = tokens[bs];
    float div = expf((float)(d & ~1) * (-9.210340371976184f / (float)D_));
    float ang = (float)s * div;
    float pe = (d & 1) ? cosf(ang) : sinf(ang);
    float v = emb[(size_t)tok * D_ + d] + pe;
    g_x[idx] = v;
    g_xb[idx] = __float2bfloat16(v);
}

// ---------------- residual + bias + LayerNorm --------------------------------
__global__ void __launch_bounds__(128) ln_kernel(const float* __restrict__ bias,
                                                 const float* __restrict__ gamma,
                                                 const float* __restrict__ beta) {
    size_t r = blockIdx.x;
    int tid = threadIdx.x;
    float4 o = *(float4*)(g_p + r * D_ + tid * 4);
    float4 xr = *(float4*)(g_x + r * D_ + tid * 4);
    float4 bb = *(const float4*)(bias + tid * 4);
    float4 y;
    y.x = o.x + xr.x + bb.x; y.y = o.y + xr.y + bb.y;
    y.z = o.z + xr.z + bb.z; y.w = o.w + xr.w + bb.w;
    __shared__ float sm[4], ss[4];
    float s = y.x + y.y + y.z + y.w;
    #pragma unroll
    for (int o2 = 16; o2; o2 >>= 1) s += __shfl_xor_sync(0xffffffffu, s, o2);
    if ((tid & 31) == 0) sm[tid >> 5] = s;
    __syncthreads();
    float mean = (sm[0] + sm[1] + sm[2] + sm[3]) * (1.0f / D_);
    float dx = y.x - mean, dy = y.y - mean, dz = y.z - mean, dw = y.w - mean;
    float sq = dx*dx + dy*dy + dz*dz + dw*dw;
    #pragma unroll
    for (int o2 = 16; o2; o2 >>= 1) sq += __shfl_xor_sync(0xffffffffu, sq, o2);
    if ((tid & 31) == 0) ss[tid >> 5] = sq;
    __syncthreads();
    float var = (ss[0] + ss[1] + ss[2] + ss[3]) * (1.0f / D_);
    float inv = rsqrtf(var + 1e-5f);
    float4 g = *(const float4*)(gamma + tid * 4);
    float4 be = *(const float4*)(beta + tid * 4);
    float4 out;
    out.x = dx * inv * g.x + be.x; out.y = dy * inv * g.y + be.y;
    out.z = dz * inv * g.z + be.z; out.w = dw * inv * g.w + be.w;
    *(float4*)(g_x + r * D_ + tid * 4) = out;
    *(__nv_bfloat162*)&g_xb[r * D_ + tid * 4]     = __floats2bfloat162_rn(out.x, out.y);
    *(__nv_bfloat162*)&g_xb[r * D_ + tid * 4 + 2] = __floats2bfloat162_rn(out.z, out.w);
}

// ---------------- mean pool / MLP ---------------------------------------------
__global__ void __launch_bounds__(512) pool_kernel() {
    int b = blockIdx.x, d = threadIdx.x;
    const float* base = g_x + (size_t)b * S_ * D_ + d;
    float s = 0.f;
    for (int i = 0; i < S_; i++) s += base[(size_t)i * D_];
    g_pool[b * D_ + d] = s * (1.0f / S_);
}

__global__ void __launch_bounds__(256) mlp1_kernel(const float* __restrict__ w,
                                                   const float* __restrict__ bias) {
    int f = blockIdx.x * 256 + threadIdx.x;
    int b = blockIdx.y;
    float acc = bias[f];
    const float* pr = g_pool + b * D_;
    for (int d = 0; d < D_; d++) acc = fmaf(pr[d], w[(size_t)d * FF_ + f], acc);
    g_h1[b * FF_ + f] = fmaxf(acc, 0.f);
}

__global__ void __launch_bounds__(192) mlp2_kernel(const float* __restrict__ w,
                                                   const float* __restrict__ bias,
                                                   float* __restrict__ out) {
    int t = threadIdx.x;
    int b = t / C_, c = t % C_;
    float acc = bias[c];
    const float* hr = g_h1 + b * FF_;
    for (int f = 0; f < FF_; f++) acc = fmaf(hr[f], w[f * C_ + c], acc);
    out[b * C_ + c] = acc;
}

// ---------------- launch ------------------------------------------------------
extern "C" void kernel_launch(void* const* d_in, const int* in_sizes, int n_in,
                              void* d_out, int out_size) {
    const int*   tokens = (const int*)d_in[0];
    const float* emb    = (const float*)d_in[1];
    const float* qkv_w  = (const float*)d_in[2];
    const float* qkv_b  = (const float*)d_in[3];
    const float* fc_w   = (const float*)d_in[4];
    const float* fc_b   = (const float*)d_in[5];
    const float* gamma  = (const float*)d_in[6];
    const float* beta   = (const float*)d_in[7];
    const float* fc1_w  = (const float*)d_in[8];
    const float* fc1_b  = (const float*)d_in[9];
    const float* fc2_w  = (const float*)d_in[10];
    const float* fc2_b  = (const float*)d_in[11];
    float* out = (float*)d_out;
    (void)in_sizes; (void)n_in; (void)out_size;

    cudaFuncSetAttribute(gemm_bf16x2, cudaFuncAttributeMaxDynamicSharedMemorySize, GSMEM);
    cudaFuncSetAttribute(flash_kernel, cudaFuncAttributeMaxDynamicSharedMemorySize, FSMEM);

    __nv_bfloat16 *xb, *qkvb, *obf;
    float *p;
    uint16_t *wh, *wl;
    cudaGetSymbolAddress((void**)&xb,   g_xb);
    cudaGetSymbolAddress((void**)&qkvb, g_qkvb);
    cudaGetSymbolAddress((void**)&obf,  g_ob);
    cudaGetSymbolAddress((void**)&p,    g_p);
    cudaGetSymbolAddress((void**)&wh,   g_wh);
    cudaGetSymbolAddress((void**)&wl,   g_wl);

    // launches 1-5 (so ncu -s 5 -c 1 profiles launch 6 = QKV GEMM layer 0)
    embed_kernel<<<(BS_ * D_) / 256, 256>>>(tokens, emb);
    convert_hl<<<(D_ * 3 * D_) / 1024, 256>>>(qkv_w, wh + WQKV_OFF(0), wl + WQKV_OFF(0));
    convert_hl<<<(D_ * D_) / 1024, 256>>>(fc_w, wh + WFC_OFF(0), wl + WFC_OFF(0));
    convert_hl<<<(D_ * 3 * D_) / 1024, 256>>>(
        qkv_w + (size_t)D_ * 3 * D_, wh + WQKV_OFF(1), wl + WQKV_OFF(1));
    convert_hl<<<(D_ * D_) / 1024, 256>>>(
        fc_w + (size_t)D_ * D_, wh + WFC_OFF(1), wl + WFC_OFF(1));

    for (int l = 0; l < L_; l++) {
        gemm_bf16x2<<<dim3(3 * D_ / 128, BS_ / 256), 256, GSMEM>>>(
            xb, wh + WQKV_OFF(l), wl + WQKV_OFF(l), qkv_b + (size_t)l * 3 * D_,
            (float*)nullptr, qkvb, 3 * D_, D_, 1);
        flash_kernel<<<dim3(S_ / 128, B_ * H_), 256, FSMEM>>>(qkvb, obf);
        gemm_bf16x2<<<dim3(D_ / 128, BS_ / 256), 256, GSMEM>>>(
            obf, wh + WFC_OFF(l), wl + WFC_OFF(l), (const float*)nullptr,
            p, (__nv_bfloat16*)nullptr, D_, D_, 0);
        ln_kernel<<<BS_, 128>>>(fc_b + (size_t)l * D_, gamma, beta);
        if (l == 0) {   // layer-2 weight converts, off the critical path
            convert_hl<<<(D_ * 3 * D_) / 1024, 256>>>(
                qkv_w + (size_t)2 * D_ * 3 * D_, wh + WQKV_OFF(2), wl + WQKV_OFF(2));
            convert_hl<<<(D_ * D_) / 1024, 256>>>(
                fc_w + (size_t)2 * D_ * D_, wh + WFC_OFF(2), wl + WFC_OFF(2));
        }
    }

    pool_kernel<<<B_, 512>>>();
    mlp1_kernel<<<dim3(FF_ / 256, B_), 256>>>(fc1_w, fc1_b);
    mlp2_kernel<<<1, B_ * C_>>>(fc2_w, fc2_b, out);
}

// round 13
// speedup vs baseline: 1.3174x; 1.3174x over previous
#include <cuda_runtime.h>
#include <cuda_bf16.h>
#include <cuda_fp16.h>
#include <math.h>
#include <stdint.h>

#define B_ 32
#define S_ 1024
#define D_ 512
#define H_ 8
#define L_ 3
#define FF_ 2048
#define C_ 6
#define BS_ (B_*S_)

// ---------------- scratch (device globals) ----------------------------------
static __device__ float          g_x[(size_t)BS_*D_];        // residual fp32
static __device__ __half         g_xb[(size_t)BS_*D_];       // residual f16
static __device__ __nv_bfloat16  g_qkvb[(size_t)BS_*3*D_];   // Q(bf16,scaled) K(bf16) V(f16 bits)
static __device__ __half         g_ob[(size_t)BS_*D_];       // attn out f16
static __device__ float          g_p[(size_t)BS_*D_];        // proj out fp32
static __device__ float          g_pool[B_*D_];
static __device__ float          g_h1[B_*FF_];
#define WQKV_OFF(l) ((size_t)(l) * (size_t)(D_*3*D_))
#define WFC_OFF(l)  ((size_t)3 * (D_*3*D_) + (size_t)(l) * (D_*D_))
#define WTOT ((size_t)3 * (D_*3*D_) + (size_t)3 * (D_*D_))
static __device__ __half         g_wf[WTOT];                 // weights f16

// ---------------- asm helpers ------------------------------------------------
__device__ __forceinline__ uint32_t s2u(const void* p) {
    return (uint32_t)__cvta_generic_to_shared(p);
}
#define LDSM4(R, addr) \
    asm volatile("ldmatrix.sync.aligned.m8n8.x4.shared.b16 {%0,%1,%2,%3}, [%4];" \
        : "=r"((R)[0]), "=r"((R)[1]), "=r"((R)[2]), "=r"((R)[3]) : "r"(addr))
#define LDSM4T(R, addr) \
    asm volatile("ldmatrix.sync.aligned.m8n8.x4.trans.shared.b16 {%0,%1,%2,%3}, [%4];" \
        : "=r"((R)[0]), "=r"((R)[1]), "=r"((R)[2]), "=r"((R)[3]) : "r"(addr))
#define MMA_BF16(c, a, b) \
    asm volatile("mma.sync.aligned.m16n8k16.row.col.f32.bf16.bf16.f32 " \
        "{%0,%1,%2,%3},{%4,%5,%6,%7},{%8,%9},{%0,%1,%2,%3};" \
        : "+f"((c)[0]), "+f"((c)[1]), "+f"((c)[2]), "+f"((c)[3]) \
        : "r"((a)[0]), "r"((a)[1]), "r"((a)[2]), "r"((a)[3]), "r"((b)[0]), "r"((b)[1]))
#define MMA_F16(c, a, b) \
    asm volatile("mma.sync.aligned.m16n8k16.row.col.f32.f16.f16.f32 " \
        "{%0,%1,%2,%3},{%4,%5,%6,%7},{%8,%9},{%0,%1,%2,%3};" \
        : "+f"((c)[0]), "+f"((c)[1]), "+f"((c)[2]), "+f"((c)[3]) \
        : "r"((a)[0]), "r"((a)[1]), "r"((a)[2]), "r"((a)[3]), "r"((b)[0]), "r"((b)[1]))
#define CP16(dst, src) \
    asm volatile("cp.async.cg.shared.global [%0], [%1], 16;" :: "r"(dst), "l"(src))
#define CP_COMMIT asm volatile("cp.async.commit_group;")
#define CP_WAIT(n) asm volatile("cp.async.wait_group %0;" :: "n"(n))
__device__ __forceinline__ uint32_t exp2_f16x2(float lo, float hi) {
    uint32_t d;
    asm("{.reg .b32 t;\n\t"
        "cvt.rn.f16x2.f32 t, %1, %2;\n\t"
        "ex2.approx.f16x2 %0, t;}"
        : "=r"(d) : "f"(hi), "f"(lo));
    return d;
}

// ---------------- fp32 -> f16 weight convert ---------------------------------
__global__ void __launch_bounds__(256) convert_f16(const float* __restrict__ in,
                                                   __half* __restrict__ outw) {
    int i = blockIdx.x * 256 + threadIdx.x;
    float4 v = ((const float4*)in)[i];
    __half2 h0 = __floats2half2_rn(v.x, v.y);
    __half2 h1 = __floats2half2_rn(v.z, v.w);
    uint2 w;
    w.x = *(uint32_t*)&h0;
    w.y = *(uint32_t*)&h1;
    ((uint2*)outw)[i] = w;
}

// ---------------- pipelined f16 GEMM (128x128 tile, 3-stage) -----------------
// C = A(f16)[M,K] @ W(f16)[K,N] + bias.
// qkvmode: Q cols (col%192<64) bf16*log2e/8, K cols bf16, V cols f16.
#define AST 40
#define BST 136
#define A_EL (128*AST)
#define B_EL (32*BST)
#define GSMEM ((3*A_EL + 3*B_EL) * 2)   // 56832 bytes
__global__ void __launch_bounds__(256, 2) gemm_f16(
    const __half* __restrict__ A, const __half* __restrict__ W,
    const float* __restrict__ bias,
    float* __restrict__ Cf, __nv_bfloat16* __restrict__ Cb,
    __half* __restrict__ Ch, int N, int K, int qkvmode) {
    extern __shared__ __align__(16) uint16_t sm_[];
    uint16_t* sA = sm_;                   // 3 x A_EL
    uint16_t* sB = sm_ + 3 * A_EL;        // 3 x B_EL
    const int tid = threadIdx.x;
    const int lane = tid & 31, warp = tid >> 5;
    const int wr = warp >> 2, wc = warp & 3;
    const size_t aRow0 = (size_t)blockIdx.y * 128;
    const int bCol0 = blockIdx.x * 128;
    const int lrow = lane & 15, lseg = lane >> 4;

    float acc[16][4];
    #pragma unroll
    for (int i = 0; i < 16; i++)
        #pragma unroll
        for (int j = 0; j < 4; j++) acc[i][j] = 0.f;

    const int nk = K / 32;
    auto load_stage = [&](int st, int kt) {
        #pragma unroll
        for (int i = 0; i < 2; i++) {
            int c = tid * 2 + i;
            int r = c >> 2, seg = c & 3;
            CP16(s2u(&sA[st * A_EL + r * AST + seg * 8]),
                 A + (aRow0 + r) * K + kt + seg * 8);
        }
        #pragma unroll
        for (int i = 0; i < 2; i++) {
            int c = tid * 2 + i;
            int r = c >> 4, seg = c & 15;
            CP16(s2u(&sB[st * B_EL + r * BST + seg * 8]),
                 W + (size_t)(kt + r) * N + bCol0 + seg * 8);
        }
    };
    load_stage(0, 0); CP_COMMIT;
    load_stage(1, 32); CP_COMMIT;

    int stC = 0, stL = 2;
    for (int it = 0; it < nk; it++) {
        if (it == nk - 1) { CP_WAIT(0); } else { CP_WAIT(1); }
        __syncthreads();
        if (it + 2 < nk) { load_stage(stL, (it + 2) * 32); CP_COMMIT; }
        if (++stL == 3) stL = 0;
        #pragma unroll
        for (int k16 = 0; k16 < 32; k16 += 16) {
            uint32_t a[4][4], bf[4][2];
            #pragma unroll
            for (int mi = 0; mi < 4; mi++)
                LDSM4(a[mi], s2u(&sA[stC * A_EL + (wr * 64 + mi * 16 + lrow) * AST + k16 + lseg * 8]));
            #pragma unroll
            for (int np = 0; np < 2; np++) {
                uint32_t t4[4];
                LDSM4T(t4, s2u(&sB[stC * B_EL + (k16 + lrow) * BST + wc * 32 + np * 16 + lseg * 8]));
                bf[np*2][0] = t4[0]; bf[np*2][1] = t4[1];
                bf[np*2+1][0] = t4[2]; bf[np*2+1][1] = t4[3];
            }
            #pragma unroll
            for (int mi = 0; mi < 4; mi++)
                #pragma unroll
                for (int ni = 0; ni < 4; ni++)
                    MMA_F16(acc[mi * 4 + ni], a[mi], bf[ni]);
        }
        if (++stC == 3) stC = 0;
    }
    #pragma unroll
    for (int mi = 0; mi < 4; mi++) {
        size_t row = aRow0 + wr * 64 + mi * 16 + (lane >> 2);
        #pragma unroll
        for (int ni = 0; ni < 4; ni++) {
            int col = bCol0 + wc * 32 + ni * 8 + (lane & 3) * 2;
            float b0 = 0.f, b1 = 0.f;
            if (bias) { b0 = bias[col]; b1 = bias[col + 1]; }
            float* c = acc[mi * 4 + ni];
            float v00 = c[0] + b0, v01 = c[1] + b1;
            float v10 = c[2] + b0, v11 = c[3] + b1;
            if (Cf) {
                *(float2*)&Cf[row * N + col] = make_float2(v00, v01);
                *(float2*)&Cf[(row + 8) * N + col] = make_float2(v10, v11);
            }
            if (Ch) {
                __half2 h0 = __floats2half2_rn(v00, v01);
                __half2 h1 = __floats2half2_rn(v10, v11);
                *(__half2*)&Ch[row * N + col] = h0;
                *(__half2*)&Ch[(row + 8) * N + col] = h1;
            }
            if (Cb) {
                uint32_t w0, w1;
                int cm = col % 192;
                if (qkvmode && cm >= 128) {           // V: f16 bits
                    __half2 h0 = __floats2half2_rn(v00, v01);
                    __half2 h1 = __floats2half2_rn(v10, v11);
                    w0 = *(uint32_t*)&h0; w1 = *(uint32_t*)&h1;
                } else {
                    // Q cols pre-scaled by log2(e)/8 so flash uses ex2 directly
                    float sc = (qkvmode && cm < 64) ? 0.1803368801f : 1.0f;
                    __nv_bfloat162 t0 = __floats2bfloat162_rn(v00 * sc, v01 * sc);
                    __nv_bfloat162 t1 = __floats2bfloat162_rn(v10 * sc, v11 * sc);
                    w0 = *(uint32_t*)&t0; w1 = *(uint32_t*)&t1;
                }
                *(uint32_t*)&Cb[row * N + col] = w0;
                *(uint32_t*)&Cb[(row + 8) * N + col] = w1;
            }
        }
    }
}

// ---------------- fused flash attention (f16 exp + mma row-sums) -------------
#define KST 72
#define FSMEM ((128*KST + 3*64*KST*2) * 2)   // 73728 bytes
__global__ void __launch_bounds__(256) flash_kernel(
    const __nv_bfloat16* __restrict__ qkvb, __half* __restrict__ ob) {
    extern __shared__ __align__(16) __nv_bfloat16 fsm_[];
    __nv_bfloat16* sQ = fsm_;
    __nv_bfloat16* sK = fsm_ + 128 * KST;
    __nv_bfloat16* sV = sK + 3 * 64 * KST;
    const int bh = blockIdx.y;
    const int b = bh >> 3, h = bh & 7;
    const int q0 = blockIdx.x * 128;
    const int tid = threadIdx.x, lane = tid & 31, warp = tid >> 5;
    const __nv_bfloat16* qb = qkvb + (size_t)(b * S_) * 1536 + h * 192;
    const __nv_bfloat16* kb = qb + 64;
    const __nv_bfloat16* vb = qb + 128;

    auto load_kv = [&](int buf, int t) {
        #pragma unroll
        for (int i = 0; i < 2; i++) {
            int c = tid + i * 256;
            int r = c >> 3, seg = c & 7;
            CP16(s2u(&sK[buf * 64 * KST + r * KST + seg * 8]),
                 kb + (size_t)(t * 64 + r) * 1536 + seg * 8);
            CP16(s2u(&sV[buf * 64 * KST + r * KST + seg * 8]),
                 vb + (size_t)(t * 64 + r) * 1536 + seg * 8);
        }
    };
    #pragma unroll
    for (int i = 0; i < 4; i++) {
        int c = tid + i * 256;
        int r = c >> 3, seg = c & 7;
        CP16(s2u(&sQ[r * KST + seg * 8]), qb + (size_t)(q0 + r) * 1536 + seg * 8);
    }
    load_kv(0, 0); CP_COMMIT;
    load_kv(1, 1); CP_COMMIT;
    CP_WAIT(1);
    __syncthreads();

    uint32_t qf[4][4];
    const int qr = warp * 16;
    #pragma unroll
    for (int kk = 0; kk < 4; kk++)
        LDSM4(qf[kk], s2u(&sQ[(qr + (lane & 15)) * KST + kk * 16 + (lane >> 4) * 8]));

    float o[8][4];
    #pragma unroll
    for (int i = 0; i < 8; i++)
        #pragma unroll
        for (int j = 0; j < 4; j++) o[i][j] = 0.f;
    float lacc[4] = {0.f, 0.f, 0.f, 0.f};
    const uint32_t onesb[2] = {0x3C003C00u, 0x3C003C00u};

    const int kRow = ((lane >> 4) & 1) * 8 + (lane & 7);
    const int kCol = ((lane >> 3) & 1) * 8;
    const int vRow = ((lane >> 3) & 1) * 8 + (lane & 7);
    const int vCol = ((lane >> 4) & 1) * 8;

    int stC = 0, stL = 2;
    for (int t = 0; t < 16; t++) {
        if (t == 15) { CP_WAIT(0); } else { CP_WAIT(1); }
        __syncthreads();
        if (t + 2 < 16) { load_kv(stL, t + 2); CP_COMMIT; }
        if (++stL == 3) stL = 0;
        const int kbuf = stC * 64 * KST;
        if (++stC == 3) stC = 0;

        float s[8][4];
        #pragma unroll
        for (int i = 0; i < 8; i++)
            #pragma unroll
            for (int j = 0; j < 4; j++) s[i][j] = 0.f;
        #pragma unroll
        for (int kk = 0; kk < 4; kk++) {
            uint32_t kf[8][2];
            #pragma unroll
            for (int nf2 = 0; nf2 < 4; nf2++) {
                uint32_t t4[4];
                LDSM4(t4, s2u(&sK[kbuf + (nf2 * 16 + kRow) * KST + kk * 16 + kCol]));
                kf[nf2*2][0] = t4[0]; kf[nf2*2][1] = t4[1];
                kf[nf2*2+1][0] = t4[2]; kf[nf2*2+1][1] = t4[3];
            }
            #pragma unroll
            for (int nf = 0; nf < 8; nf++)
                MMA_BF16(s[nf], qf[kk], kf[nf]);
        }

        uint32_t pa[4][4];
        #pragma unroll
        for (int kk = 0; kk < 4; kk++) {
            pa[kk][0] = exp2_f16x2(s[2*kk][0],   s[2*kk][1]);
            pa[kk][1] = exp2_f16x2(s[2*kk][2],   s[2*kk][3]);
            pa[kk][2] = exp2_f16x2(s[2*kk+1][0], s[2*kk+1][1]);
            pa[kk][3] = exp2_f16x2(s[2*kk+1][2], s[2*kk+1][3]);
            MMA_F16(lacc, pa[kk], onesb);
        }

        #pragma unroll
        for (int kk = 0; kk < 4; kk++) {
            uint32_t vf[8][2];
            #pragma unroll
            for (int nf2 = 0; nf2 < 4; nf2++) {
                uint32_t t4[4];
                LDSM4T(t4, s2u(&sV[kbuf + (kk * 16 + vRow) * KST + nf2 * 16 + vCol]));
                vf[nf2*2][0] = t4[0]; vf[nf2*2][1] = t4[1];
                vf[nf2*2+1][0] = t4[2]; vf[nf2*2+1][1] = t4[3];
            }
            #pragma unroll
            for (int nf = 0; nf < 8; nf++)
                MMA_F16(o[nf], pa[kk], vf[nf]);
        }
    }

    float inv0 = 1.f / lacc[0], inv1 = 1.f / lacc[2];
    size_t r0 = (size_t)b * S_ + q0 + qr + (lane >> 2);
    size_t r1 = r0 + 8;
    #pragma unroll
    for (int nf = 0; nf < 8; nf++) {
        int col = h * 64 + nf * 8 + (lane & 3) * 2;
        *(__half2*)&ob[r0 * D_ + col] =
            __floats2half2_rn(o[nf][0] * inv0, o[nf][1] * inv0);
        *(__half2*)&ob[r1 * D_ + col] =
            __floats2half2_rn(o[nf][2] * inv1, o[nf][3] * inv1);
    }
}

// ---------------- embedding + sinusoidal PE ----------------------------------
__global__ void __launch_bounds__(256) embed_kernel(const int* __restrict__ tokens,
                                                    const float* __restrict__ emb) {
    int idx = blockIdx.x * 256 + threadIdx.x;
    int d = idx & (D_ - 1);
    int bs = idx >> 9;
    int s = bs & (S_ - 1);
    int tok = tokens[bs];
    float div = expf((float)(d & ~1) * (-9.210340371976184f / (float)D_));
    float ang = (float)s * div;
    float pe = (d & 1) ? cosf(ang) : sinf(ang);
    float v = emb[(size_t)tok * D_ + d] + pe;
    g_x[idx] = v;
    g_xb[idx] = __float2half(v);
}

// ---------------- residual + bias + LayerNorm --------------------------------
__global__ void __launch_bounds__(128) ln_kernel(const float* __restrict__ bias,
                                                 const float* __restrict__ gamma,
                                                 const float* __restrict__ beta) {
    size_t r = blockIdx.x;
    int tid = threadIdx.x;
    float4 o = *(float4*)(g_p + r * D_ + tid * 4);
    float4 xr = *(float4*)(g_x + r * D_ + tid * 4);
    float4 bb = *(const float4*)(bias + tid * 4);
    float4 y;
    y.x = o.x + xr.x + bb.x; y.y = o.y + xr.y + bb.y;
    y.z = o.z + xr.z + bb.z; y.w = o.w + xr.w + bb.w;
    __shared__ float sm[4], ss[4];
    float s = y.x + y.y + y.z + y.w;
    #pragma unroll
    for (int o2 = 16; o2; o2 >>= 1) s += __shfl_xor_sync(0xffffffffu, s, o2);
    if ((tid & 31) == 0) sm[tid >> 5] = s;
    __syncthreads();
    float mean = (sm[0] + sm[1] + sm[2] + sm[3]) * (1.0f / D_);
    float dx = y.x - mean, dy = y.y - mean, dz = y.z - mean, dw = y.w - mean;
    float sq = dx*dx + dy*dy + dz*dz + dw*dw;
    #pragma unroll
    for (int o2 = 16; o2; o2 >>= 1) sq += __shfl_xor_sync(0xffffffffu, sq, o2);
    if ((tid & 31) == 0) ss[tid >> 5] = sq;
    __syncthreads();
    float var = (ss[0] + ss[1] + ss[2] + ss[3]) * (1.0f / D_);
    float inv = rsqrtf(var + 1e-5f);
    float4 g = *(const float4*)(gamma + tid * 4);
    float4 be = *(const float4*)(beta + tid * 4);
    float4 out;
    out.x = dx * inv * g.x + be.x; out.y = dy * inv * g.y + be.y;
    out.z = dz * inv * g.z + be.z; out.w = dw * inv * g.w + be.w;
    *(float4*)(g_x + r * D_ + tid * 4) = out;
    *(__half2*)&g_xb[r * D_ + tid * 4]     = __floats2half2_rn(out.x, out.y);
    *(__half2*)&g_xb[r * D_ + tid * 4 + 2] = __floats2half2_rn(out.z, out.w);
}

// ---------------- mean pool / MLP ---------------------------------------------
__global__ void __launch_bounds__(512) pool_kernel() {
    int b = blockIdx.x, d = threadIdx.x;
    const float* base = g_x + (size_t)b * S_ * D_ + d;
    float s = 0.f;
    for (int i = 0; i < S_; i++) s += base[(size_t)i * D_];
    g_pool[b * D_ + d] = s * (1.0f / S_);
}

__global__ void __launch_bounds__(256) mlp1_kernel(const float* __restrict__ w,
                                                   const float* __restrict__ bias) {
    int f = blockIdx.x * 256 + threadIdx.x;
    int b = blockIdx.y;
    float acc = bias[f];
    const float* pr = g_pool + b * D_;
    for (int d = 0; d < D_; d++) acc = fmaf(pr[d], w[(size_t)d * FF_ + f], acc);
    g_h1[b * FF_ + f] = fmaxf(acc, 0.f);
}

__global__ void __launch_bounds__(192) mlp2_kernel(const float* __restrict__ w,
                                                   const float* __restrict__ bias,
                                                   float* __restrict__ out) {
    int t = threadIdx.x;
    int b = t / C_, c = t % C_;
    float acc = bias[c];
    const float* hr = g_h1 + b * FF_;
    for (int f = 0; f < FF_; f++) acc = fmaf(hr[f], w[f * C_ + c], acc);
    out[b * C_ + c] = acc;
}

// ---------------- launch ------------------------------------------------------
extern "C" void kernel_launch(void* const* d_in, const int* in_sizes, int n_in,
                              void* d_out, int out_size) {
    const int*   tokens = (const int*)d_in[0];
    const float* emb    = (const float*)d_in[1];
    const float* qkv_w  = (const float*)d_in[2];
    const float* qkv_b  = (const float*)d_in[3];
    const float* fc_w   = (const float*)d_in[4];
    const float* fc_b   = (const float*)d_in[5];
    const float* gamma  = (const float*)d_in[6];
    const float* beta   = (const float*)d_in[7];
    const float* fc1_w  = (const float*)d_in[8];
    const float* fc1_b  = (const float*)d_in[9];
    const float* fc2_w  = (const float*)d_in[10];
    const float* fc2_b  = (const float*)d_in[11];
    float* out = (float*)d_out;
    (void)in_sizes; (void)n_in; (void)out_size;

    cudaFuncSetAttribute(gemm_f16, cudaFuncAttributeMaxDynamicSharedMemorySize, GSMEM);
    cudaFuncSetAttribute(flash_kernel, cudaFuncAttributeMaxDynamicSharedMemorySize, FSMEM);

    __half *xb, *obf, *wf;
    __nv_bfloat16 *qkvb;
    float *p;
    cudaGetSymbolAddress((void**)&xb,   g_xb);
    cudaGetSymbolAddress((void**)&qkvb, g_qkvb);
    cudaGetSymbolAddress((void**)&obf,  g_ob);
    cudaGetSymbolAddress((void**)&p,    g_p);
    cudaGetSymbolAddress((void**)&wf,   g_wf);

    embed_kernel<<<(BS_ * D_) / 256, 256>>>(tokens, emb);
    for (int l = 0; l < L_; l++) {
        convert_f16<<<(D_ * 3 * D_) / 1024, 256>>>(
            qkv_w + (size_t)l * D_ * 3 * D_, wf + WQKV_OFF(l));
        convert_f16<<<(D_ * D_) / 1024, 256>>>(
            fc_w + (size_t)l * D_ * D_, wf + WFC_OFF(l));
    }

    for (int l = 0; l < L_; l++) {
        gemm_f16<<<dim3(3 * D_ / 128, BS_ / 128), 256, GSMEM>>>(
            xb, wf + WQKV_OFF(l), qkv_b + (size_t)l * 3 * D_,
            (float*)nullptr, qkvb, (__half*)nullptr, 3 * D_, D_, 1);
        flash_kernel<<<dim3(S_ / 128, B_ * H_), 256, FSMEM>>>(qkvb, obf);
        gemm_f16<<<dim3(D_ / 128, BS_ / 128), 256, GSMEM>>>(
            obf, wf + WFC_OFF(l), (const float*)nullptr,
            p, (__nv_bfloat16*)nullptr, (__half*)nullptr, D_, D_, 0);
        ln_kernel<<<BS_, 128>>>(fc_b + (size_t)l * D_, gamma, beta);
    }

    pool_kernel<<<B_, 512>>>();
    mlp1_kernel<<<dim3(FF_ / 256, B_), 256>>>(fc1_w, fc1_b);
    mlp2_kernel<<<1, B_ * C_>>>(fc2_w, fc2_b, out);
}

// round 15
// speedup vs baseline: 1.3979x; 1.0611x over previous
#include <cuda_runtime.h>
#include <cuda_bf16.h>
#include <cuda_fp16.h>
#include <math.h>
#include <stdint.h>

#define B_ 32
#define S_ 1024
#define D_ 512
#define H_ 8
#define L_ 3
#define FF_ 2048
#define C_ 6
#define BS_ (B_*S_)

// ---------------- scratch (device globals) ----------------------------------
static __device__ float          g_x[(size_t)BS_*D_];        // residual fp32
static __device__ __half         g_xb[(size_t)BS_*D_];       // residual f16
static __device__ __nv_bfloat16  g_qkvb[(size_t)BS_*3*D_];   // Q(bf16,scaled) K(bf16) V(f16 bits)
static __device__ __half         g_ob[(size_t)BS_*D_];       // attn out f16
static __device__ float          g_p[(size_t)BS_*D_];        // proj+bias+residual fp32
static __device__ float          g_pool[B_*D_];
static __device__ float          g_h1[B_*FF_];
#define WQKV_OFF(l) ((size_t)(l) * (size_t)(D_*3*D_))
#define WFC_OFF(l)  ((size_t)3 * (D_*3*D_) + (size_t)(l) * (D_*D_))
#define WTOT ((size_t)3 * (D_*3*D_) + (size_t)3 * (D_*D_))
static __device__ __half         g_wf[WTOT];                 // weights f16

// ---------------- asm helpers ------------------------------------------------
__device__ __forceinline__ uint32_t s2u(const void* p) {
    return (uint32_t)__cvta_generic_to_shared(p);
}
#define LDSM4(R, addr) \
    asm volatile("ldmatrix.sync.aligned.m8n8.x4.shared.b16 {%0,%1,%2,%3}, [%4];" \
        : "=r"((R)[0]), "=r"((R)[1]), "=r"((R)[2]), "=r"((R)[3]) : "r"(addr))
#define LDSM4T(R, addr) \
    asm volatile("ldmatrix.sync.aligned.m8n8.x4.trans.shared.b16 {%0,%1,%2,%3}, [%4];" \
        : "=r"((R)[0]), "=r"((R)[1]), "=r"((R)[2]), "=r"((R)[3]) : "r"(addr))
#define MMA_BF16(c, a, b) \
    asm volatile("mma.sync.aligned.m16n8k16.row.col.f32.bf16.bf16.f32 " \
        "{%0,%1,%2,%3},{%4,%5,%6,%7},{%8,%9},{%0,%1,%2,%3};" \
        : "+f"((c)[0]), "+f"((c)[1]), "+f"((c)[2]), "+f"((c)[3]) \
        : "r"((a)[0]), "r"((a)[1]), "r"((a)[2]), "r"((a)[3]), "r"((b)[0]), "r"((b)[1]))
#define MMA_F16(c, a, b) \
    asm volatile("mma.sync.aligned.m16n8k16.row.col.f32.f16.f16.f32 " \
        "{%0,%1,%2,%3},{%4,%5,%6,%7},{%8,%9},{%0,%1,%2,%3};" \
        : "+f"((c)[0]), "+f"((c)[1]), "+f"((c)[2]), "+f"((c)[3]) \
        : "r"((a)[0]), "r"((a)[1]), "r"((a)[2]), "r"((a)[3]), "r"((b)[0]), "r"((b)[1]))
#define CP16(dst, src) \
    asm volatile("cp.async.cg.shared.global [%0], [%1], 16;" :: "r"(dst), "l"(src))
#define CP_COMMIT asm volatile("cp.async.commit_group;")
#define CP_WAIT(n) asm volatile("cp.async.wait_group %0;" :: "n"(n))
__device__ __forceinline__ uint32_t exp2_f16x2(float lo, float hi) {
    uint32_t d;
    asm("{.reg .b32 t;\n\t"
        "cvt.rn.f16x2.f32 t, %1, %2;\n\t"
        "ex2.approx.f16x2 %0, t;}"
        : "=r"(d) : "f"(hi), "f"(lo));
    return d;
}

// ---------------- fp32 -> f16 weight convert ---------------------------------
__global__ void __launch_bounds__(256) convert_f16(const float* __restrict__ in,
                                                   __half* __restrict__ outw) {
    int i = blockIdx.x * 256 + threadIdx.x;
    float4 v = ((const float4*)in)[i];
    __half2 h0 = __floats2half2_rn(v.x, v.y);
    __half2 h1 = __floats2half2_rn(v.z, v.w);
    uint2 w;
    w.x = *(uint32_t*)&h0;
    w.y = *(uint32_t*)&h1;
    ((uint2*)outw)[i] = w;
}

// ---------------- pipelined f16 GEMM (128x128 tile, k-chunk 64, 3-stage) -----
// C = A(f16)[M,K] @ W(f16)[K,N] + bias (+ residual Res).
// qkvmode: Q cols (col%192<64) bf16*log2e/8, K cols bf16, V cols f16.
#define AST 72                        // 64 k-elems + 8 pad (144B rows)
#define BST 136
#define A_EL (128*AST)                // per stage
#define B_EL (64*BST)
#define GSMEM ((3*A_EL + 3*B_EL) * 2) // 107520 bytes (2 CTAs/SM = 210KB)
__global__ void __launch_bounds__(256, 2) gemm_f16(
    const __half* __restrict__ A, const __half* __restrict__ W,
    const float* __restrict__ bias, const float* __restrict__ Res,
    float* __restrict__ Cf, __nv_bfloat16* __restrict__ Cb, int N, int K,
    int qkvmode) {
    extern __shared__ __align__(16) uint16_t sm_[];
    uint16_t* sA = sm_;                   // 3 x A_EL
    uint16_t* sB = sm_ + 3 * A_EL;        // 3 x B_EL
    const int tid = threadIdx.x;
    const int lane = tid & 31, warp = tid >> 5;
    const int wr = warp >> 2, wc = warp & 3;
    const size_t aRow0 = (size_t)blockIdx.y * 128;
    const int bCol0 = blockIdx.x * 128;
    const int lrow = lane & 15, lseg = lane >> 4;

    float acc[16][4];
    #pragma unroll
    for (int i = 0; i < 16; i++)
        #pragma unroll
        for (int j = 0; j < 4; j++) acc[i][j] = 0.f;

    const int nk = K / 64;
    auto load_stage = [&](int st, int kt) {
        #pragma unroll
        for (int i = 0; i < 4; i++) {                  // A: 128x64 = 1024 chunks
            int c = tid + i * 256;
            int r = c >> 3, seg = c & 7;
            CP16(s2u(&sA[st * A_EL + r * AST + seg * 8]),
                 A + (aRow0 + r) * K + kt + seg * 8);
        }
        #pragma unroll
        for (int i = 0; i < 4; i++) {                  // B: 64x128 = 1024 chunks
            int c = tid + i * 256;
            int r = c >> 4, seg = c & 15;
            CP16(s2u(&sB[st * B_EL + r * BST + seg * 8]),
                 W + (size_t)(kt + r) * N + bCol0 + seg * 8);
        }
    };
    load_stage(0, 0); CP_COMMIT;
    load_stage(1, 64); CP_COMMIT;

    int stC = 0, stL = 2;
    for (int it = 0; it < nk; it++) {
        if (it == nk - 1) { CP_WAIT(0); } else { CP_WAIT(1); }
        __syncthreads();
        if (it + 2 < nk) { load_stage(stL, (it + 2) * 64); CP_COMMIT; }
        if (++stL == 3) stL = 0;
        #pragma unroll
        for (int k16 = 0; k16 < 64; k16 += 16) {
            uint32_t a[4][4], bf[4][2];
            #pragma unroll
            for (int mi = 0; mi < 4; mi++)
                LDSM4(a[mi], s2u(&sA[stC * A_EL + (wr * 64 + mi * 16 + lrow) * AST + k16 + lseg * 8]));
            #pragma unroll
            for (int np = 0; np < 2; np++) {
                uint32_t t4[4];
                LDSM4T(t4, s2u(&sB[stC * B_EL + (k16 + lrow) * BST + wc * 32 + np * 16 + lseg * 8]));
                bf[np*2][0] = t4[0]; bf[np*2][1] = t4[1];
                bf[np*2+1][0] = t4[2]; bf[np*2+1][1] = t4[3];
            }
            #pragma unroll
            for (int mi = 0; mi < 4; mi++)
                #pragma unroll
                for (int ni = 0; ni < 4; ni++)
                    MMA_F16(acc[mi * 4 + ni], a[mi], bf[ni]);
        }
        if (++stC == 3) stC = 0;
    }
    #pragma unroll
    for (int mi = 0; mi < 4; mi++) {
        size_t row = aRow0 + wr * 64 + mi * 16 + (lane >> 2);
        #pragma unroll
        for (int ni = 0; ni < 4; ni++) {
            int col = bCol0 + wc * 32 + ni * 8 + (lane & 3) * 2;
            float b0 = 0.f, b1 = 0.f;
            if (bias) { b0 = bias[col]; b1 = bias[col + 1]; }
            float* c = acc[mi * 4 + ni];
            float v00 = c[0] + b0, v01 = c[1] + b1;
            float v10 = c[2] + b0, v11 = c[3] + b1;
            if (Res) {
                float2 r0 = *(const float2*)&Res[row * N + col];
                float2 r1 = *(const float2*)&Res[(row + 8) * N + col];
                v00 += r0.x; v01 += r0.y;
                v10 += r1.x; v11 += r1.y;
            }
            if (Cf) {
                *(float2*)&Cf[row * N + col] = make_float2(v00, v01);
                *(float2*)&Cf[(row + 8) * N + col] = make_float2(v10, v11);
            }
            if (Cb) {
                uint32_t w0, w1;
                int cm = col % 192;
                if (qkvmode && cm >= 128) {           // V: f16 bits
                    __half2 h0 = __floats2half2_rn(v00, v01);
                    __half2 h1 = __floats2half2_rn(v10, v11);
                    w0 = *(uint32_t*)&h0; w1 = *(uint32_t*)&h1;
                } else {
                    float sc = (qkvmode && cm < 64) ? 0.1803368801f : 1.0f;
                    __nv_bfloat162 t0 = __floats2bfloat162_rn(v00 * sc, v01 * sc);
                    __nv_bfloat162 t1 = __floats2bfloat162_rn(v10 * sc, v11 * sc);
                    w0 = *(uint32_t*)&t0; w1 = *(uint32_t*)&t1;
                }
                *(uint32_t*)&Cb[row * N + col] = w0;
                *(uint32_t*)&Cb[(row + 8) * N + col] = w1;
            }
        }
    }
}

// ---------------- fused flash attention (f16 exp + mma row-sums) -------------
#define KST 72
#define FSMEM ((128*KST + 3*64*KST*2) * 2)   // 73728 bytes
__global__ void __launch_bounds__(256) flash_kernel(
    const __nv_bfloat16* __restrict__ qkvb, __half* __restrict__ ob) {
    extern __shared__ __align__(16) __nv_bfloat16 fsm_[];
    __nv_bfloat16* sQ = fsm_;
    __nv_bfloat16* sK = fsm_ + 128 * KST;
    __nv_bfloat16* sV = sK + 3 * 64 * KST;
    const int bh = blockIdx.y;
    const int b = bh >> 3, h = bh & 7;
    const int q0 = blockIdx.x * 128;
    const int tid = threadIdx.x, lane = tid & 31, warp = tid >> 5;
    const __nv_bfloat16* qb = qkvb + (size_t)(b * S_) * 1536 + h * 192;
    const __nv_bfloat16* kb = qb + 64;
    const __nv_bfloat16* vb = qb + 128;

    auto load_kv = [&](int buf, int t) {
        #pragma unroll
        for (int i = 0; i < 2; i++) {
            int c = tid + i * 256;
            int r = c >> 3, seg = c & 7;
            CP16(s2u(&sK[buf * 64 * KST + r * KST + seg * 8]),
                 kb + (size_t)(t * 64 + r) * 1536 + seg * 8);
            CP16(s2u(&sV[buf * 64 * KST + r * KST + seg * 8]),
                 vb + (size_t)(t * 64 + r) * 1536 + seg * 8);
        }
    };
    #pragma unroll
    for (int i = 0; i < 4; i++) {
        int c = tid + i * 256;
        int r = c >> 3, seg = c & 7;
        CP16(s2u(&sQ[r * KST + seg * 8]), qb + (size_t)(q0 + r) * 1536 + seg * 8);
    }
    load_kv(0, 0); CP_COMMIT;
    load_kv(1, 1); CP_COMMIT;
    CP_WAIT(1);
    __syncthreads();

    uint32_t qf[4][4];
    const int qr = warp * 16;
    #pragma unroll
    for (int kk = 0; kk < 4; kk++)
        LDSM4(qf[kk], s2u(&sQ[(qr + (lane & 15)) * KST + kk * 16 + (lane >> 4) * 8]));

    float o[8][4];
    #pragma unroll
    for (int i = 0; i < 8; i++)
        #pragma unroll
        for (int j = 0; j < 4; j++) o[i][j] = 0.f;
    float lacc[4] = {0.f, 0.f, 0.f, 0.f};
    const uint32_t onesb[2] = {0x3C003C00u, 0x3C003C00u};

    const int kRow = ((lane >> 4) & 1) * 8 + (lane & 7);
    const int kCol = ((lane >> 3) & 1) * 8;
    const int vRow = ((lane >> 3) & 1) * 8 + (lane & 7);
    const int vCol = ((lane >> 4) & 1) * 8;

    int stC = 0, stL = 2;
    for (int t = 0; t < 16; t++) {
        if (t == 15) { CP_WAIT(0); } else { CP_WAIT(1); }
        __syncthreads();
        if (t + 2 < 16) { load_kv(stL, t + 2); CP_COMMIT; }
        if (++stL == 3) stL = 0;
        const int kbuf = stC * 64 * KST;
        if (++stC == 3) stC = 0;

        float s[8][4];
        #pragma unroll
        for (int i = 0; i < 8; i++)
            #pragma unroll
            for (int j = 0; j < 4; j++) s[i][j] = 0.f;
        #pragma unroll
        for (int kk = 0; kk < 4; kk++) {
            uint32_t kf[8][2];
            #pragma unroll
            for (int nf2 = 0; nf2 < 4; nf2++) {
                uint32_t t4[4];
                LDSM4(t4, s2u(&sK[kbuf + (nf2 * 16 + kRow) * KST + kk * 16 + kCol]));
                kf[nf2*2][0] = t4[0]; kf[nf2*2][1] = t4[1];
                kf[nf2*2+1][0] = t4[2]; kf[nf2*2+1][1] = t4[3];
            }
            #pragma unroll
            for (int nf = 0; nf < 8; nf++)
                MMA_BF16(s[nf], qf[kk], kf[nf]);
        }

        uint32_t pa[4][4];
        #pragma unroll
        for (int kk = 0; kk < 4; kk++) {
            pa[kk][0] = exp2_f16x2(s[2*kk][0],   s[2*kk][1]);
            pa[kk][1] = exp2_f16x2(s[2*kk][2],   s[2*kk][3]);
            pa[kk][2] = exp2_f16x2(s[2*kk+1][0], s[2*kk+1][1]);
            pa[kk][3] = exp2_f16x2(s[2*kk+1][2], s[2*kk+1][3]);
            MMA_F16(lacc, pa[kk], onesb);
        }

        #pragma unroll
        for (int kk = 0; kk < 4; kk++) {
            uint32_t vf[8][2];
            #pragma unroll
            for (int nf2 = 0; nf2 < 4; nf2++) {
                uint32_t t4[4];
                LDSM4T(t4, s2u(&sV[kbuf + (kk * 16 + vRow) * KST + nf2 * 16 + vCol]));
                vf[nf2*2][0] = t4[0]; vf[nf2*2][1] = t4[1];
                vf[nf2*2+1][0] = t4[2]; vf[nf2*2+1][1] = t4[3];
            }
            #pragma unroll
            for (int nf = 0; nf < 8; nf++)
                MMA_F16(o[nf], pa[kk], vf[nf]);
        }
    }

    float inv0 = 1.f / lacc[0], inv1 = 1.f / lacc[2];
    size_t r0 = (size_t)b * S_ + q0 + qr + (lane >> 2);
    size_t r1 = r0 + 8;
    #pragma unroll
    for (int nf = 0; nf < 8; nf++) {
        int col = h * 64 + nf * 8 + (lane & 3) * 2;
        *(__half2*)&ob[r0 * D_ + col] =
            __floats2half2_rn(o[nf][0] * inv0, o[nf][1] * inv0);
        *(__half2*)&ob[r1 * D_ + col] =
            __floats2half2_rn(o[nf][2] * inv1, o[nf][3] * inv1);
    }
}

// ---------------- embedding + sinusoidal PE ----------------------------------
__global__ void __launch_bounds__(256) embed_kernel(const int* __restrict__ tokens,
                                                    const float* __restrict__ emb) {
    int idx = blockIdx.x * 256 + threadIdx.x;
    int d = idx & (D_ - 1);
    int bs = idx >> 9;
    int s = bs & (S_ - 1);
    int tok = tokens[bs];
    float div = expf((float)(d & ~1) * (-9.210340371976184f / (float)D_));
    float ang = (float)s * div;
    float pe = (d & 1) ? cosf(ang) : sinf(ang);
    float v = emb[(size_t)tok * D_ + d] + pe;
    g_x[idx] = v;
    g_xb[idx] = __float2half(v);
}

// ---------------- LayerNorm (input y pre-summed: proj+bias+residual) ---------
__global__ void __launch_bounds__(128) ln_kernel(const float* __restrict__ gamma,
                                                 const float* __restrict__ beta) {
    size_t r = blockIdx.x;
    int tid = threadIdx.x;
    float4 y = *(float4*)(g_p + r * D_ + tid * 4);
    __shared__ float sm[4], ss[4];
    float s = y.x + y.y + y.z + y.w;
    #pragma unroll
    for (int o2 = 16; o2; o2 >>= 1) s += __shfl_xor_sync(0xffffffffu, s, o2);
    if ((tid & 31) == 0) sm[tid >> 5] = s;
    __syncthreads();
    float mean = (sm[0] + sm[1] + sm[2] + sm[3]) * (1.0f / D_);
    float dx = y.x - mean, dy = y.y - mean, dz = y.z - mean, dw = y.w - mean;
    float sq = dx*dx + dy*dy + dz*dz + dw*dw;
    #pragma unroll
    for (int o2 = 16; o2; o2 >>= 1) sq += __shfl_xor_sync(0xffffffffu, sq, o2);
    if ((tid & 31) == 0) ss[tid >> 5] = sq;
    __syncthreads();
    float var = (ss[0] + ss[1] + ss[2] + ss[3]) * (1.0f / D_);
    float inv = rsqrtf(var + 1e-5f);
    float4 g = *(const float4*)(gamma + tid * 4);
    float4 be = *(const float4*)(beta + tid * 4);
    float4 out;
    out.x = dx * inv * g.x + be.x; out.y = dy * inv * g.y + be.y;
    out.z = dz * inv * g.z + be.z; out.w = dw * inv * g.w + be.w;
    *(float4*)(g_x + r * D_ + tid * 4) = out;
    *(__half2*)&g_xb[r * D_ + tid * 4]     = __floats2half2_rn(out.x, out.y);
    *(__half2*)&g_xb[r * D_ + tid * 4 + 2] = __floats2half2_rn(out.z, out.w);
}

// ---------------- mean pool / MLP ---------------------------------------------
__global__ void __launch_bounds__(512) pool_kernel() {
    int b = blockIdx.x, d = threadIdx.x;
    const float* base = g_x + (size_t)b * S_ * D_ + d;
    float s = 0.f;
    for (int i = 0; i < S_; i++) s += base[(size_t)i * D_];
    g_pool[b * D_ + d] = s * (1.0f / S_);
}

__global__ void __launch_bounds__(256) mlp1_kernel(const float* __restrict__ w,
                                                   const float* __restrict__ bias) {
    int f = blockIdx.x * 256 + threadIdx.x;
    int b = blockIdx.y;
    float acc = bias[f];
    const float* pr = g_pool + b * D_;
    for (int d = 0; d < D_; d++) acc = fmaf(pr[d], w[(size_t)d * FF_ + f], acc);
    g_h1[b * FF_ + f] = fmaxf(acc, 0.f);
}

__global__ void __launch_bounds__(192) mlp2_kernel(const float* __restrict__ w,
                                                   const float* __restrict__ bias,
                                                   float* __restrict__ out) {
    int t = threadIdx.x;
    int b = t / C_, c = t % C_;
    float acc = bias[c];
    const float* hr = g_h1 + b * FF_;
    for (int f = 0; f < FF_; f++) acc = fmaf(hr[f], w[f * C_ + c], acc);
    out[b * C_ + c] = acc;
}

// ---------------- launch ------------------------------------------------------
extern "C" void kernel_launch(void* const* d_in, const int* in_sizes, int n_in,
                              void* d_out, int out_size) {
    const int*   tokens = (const int*)d_in[0];
    const float* emb    = (const float*)d_in[1];
    const float* qkv_w  = (const float*)d_in[2];
    const float* qkv_b  = (const float*)d_in[3];
    const float* fc_w   = (const float*)d_in[4];
    const float* fc_b   = (const float*)d_in[5];
    const float* gamma  = (const float*)d_in[6];
    const float* beta   = (const float*)d_in[7];
    const float* fc1_w  = (const float*)d_in[8];
    const float* fc1_b  = (const float*)d_in[9];
    const float* fc2_w  = (const float*)d_in[10];
    const float* fc2_b  = (const float*)d_in[11];
    float* out = (float*)d_out;
    (void)in_sizes; (void)n_in; (void)out_size;

    cudaFuncSetAttribute(gemm_f16, cudaFuncAttributeMaxDynamicSharedMemorySize, GSMEM);
    cudaFuncSetAttribute(flash_kernel, cudaFuncAttributeMaxDynamicSharedMemorySize, FSMEM);

    __half *xb, *obf, *wf;
    __nv_bfloat16 *qkvb;
    float *x, *p;
    cudaGetSymbolAddress((void**)&x,    g_x);
    cudaGetSymbolAddress((void**)&xb,   g_xb);
    cudaGetSymbolAddress((void**)&qkvb, g_qkvb);
    cudaGetSymbolAddress((void**)&obf,  g_ob);
    cudaGetSymbolAddress((void**)&p,    g_p);
    cudaGetSymbolAddress((void**)&wf,   g_wf);

    embed_kernel<<<(BS_ * D_) / 256, 256>>>(tokens, emb);
    for (int l = 0; l < L_; l++) {
        convert_f16<<<(D_ * 3 * D_) / 1024, 256>>>(
            qkv_w + (size_t)l * D_ * 3 * D_, wf + WQKV_OFF(l));
        convert_f16<<<(D_ * D_) / 1024, 256>>>(
            fc_w + (size_t)l * D_ * D_, wf + WFC_OFF(l));
    }

    for (int l = 0; l < L_; l++) {
        gemm_f16<<<dim3(3 * D_ / 128, BS_ / 128), 256, GSMEM>>>(
            xb, wf + WQKV_OFF(l), qkv_b + (size_t)l * 3 * D_, (const float*)nullptr,
            (float*)nullptr, qkvb, 3 * D_, D_, 1);
        flash_kernel<<<dim3(S_ / 128, B_ * H_), 256, FSMEM>>>(qkvb, obf);
        // proj + fc_b + residual fused into epilogue -> g_p
        gemm_f16<<<dim3(D_ / 128, BS_ / 128), 256, GSMEM>>>(
            obf, wf + WFC_OFF(l), fc_b + (size_t)l * D_, x,
            p, (__nv_bfloat16*)nullptr, D_, D_, 0);
        ln_kernel<<<BS_, 128>>>(gamma, beta);
    }

    pool_kernel<<<B_, 512>>>();
    mlp1_kernel<<<dim3(FF_ / 256, B_), 256>>>(fc1_w, fc1_b);
    mlp2_kernel<<<1, B_ * C_>>>(fc2_w, fc2_b, out);
}

// round 16
// speedup vs baseline: 1.4055x; 1.0054x over previous
#include <cuda_runtime.h>
#include <cuda_bf16.h>
#include <cuda_fp16.h>
#include <math.h>
#include <stdint.h>

#define B_ 32
#define S_ 1024
#define D_ 512
#define H_ 8
#define L_ 3
#define FF_ 2048
#define C_ 6
#define BS_ (B_*S_)

// ---------------- scratch (device globals) ----------------------------------
static __device__ float          g_x[(size_t)BS_*D_];        // residual fp32
static __device__ __half         g_xb[(size_t)BS_*D_];       // residual f16
static __device__ __nv_bfloat16  g_qkvb[(size_t)BS_*3*D_];   // Q(bf16,scaled) K(bf16) V(f16 bits)
static __device__ __half         g_ob[(size_t)BS_*D_];       // attn out f16
static __device__ float          g_p[(size_t)BS_*D_];        // proj+bias+residual fp32
static __device__ float          g_pool[B_*D_];
static __device__ float          g_h1[B_*FF_];
#define WQKV_OFF(l) ((size_t)(l) * (size_t)(D_*3*D_))
#define WFC_OFF(l)  ((size_t)3 * (D_*3*D_) + (size_t)(l) * (D_*D_))
#define WTOT ((size_t)3 * (D_*3*D_) + (size_t)3 * (D_*D_))
static __device__ __half         g_wf[WTOT];                 // weights f16

// ---------------- asm helpers ------------------------------------------------
__device__ __forceinline__ uint32_t s2u(const void* p) {
    return (uint32_t)__cvta_generic_to_shared(p);
}
#define LDSM4(R, addr) \
    asm volatile("ldmatrix.sync.aligned.m8n8.x4.shared.b16 {%0,%1,%2,%3}, [%4];" \
        : "=r"((R)[0]), "=r"((R)[1]), "=r"((R)[2]), "=r"((R)[3]) : "r"(addr))
#define LDSM4T(R, addr) \
    asm volatile("ldmatrix.sync.aligned.m8n8.x4.trans.shared.b16 {%0,%1,%2,%3}, [%4];" \
        : "=r"((R)[0]), "=r"((R)[1]), "=r"((R)[2]), "=r"((R)[3]) : "r"(addr))
#define MMA_BF16(c, a, b) \
    asm volatile("mma.sync.aligned.m16n8k16.row.col.f32.bf16.bf16.f32 " \
        "{%0,%1,%2,%3},{%4,%5,%6,%7},{%8,%9},{%0,%1,%2,%3};" \
        : "+f"((c)[0]), "+f"((c)[1]), "+f"((c)[2]), "+f"((c)[3]) \
        : "r"((a)[0]), "r"((a)[1]), "r"((a)[2]), "r"((a)[3]), "r"((b)[0]), "r"((b)[1]))
#define MMA_F16(c, a, b) \
    asm volatile("mma.sync.aligned.m16n8k16.row.col.f32.f16.f16.f32 " \
        "{%0,%1,%2,%3},{%4,%5,%6,%7},{%8,%9},{%0,%1,%2,%3};" \
        : "+f"((c)[0]), "+f"((c)[1]), "+f"((c)[2]), "+f"((c)[3]) \
        : "r"((a)[0]), "r"((a)[1]), "r"((a)[2]), "r"((a)[3]), "r"((b)[0]), "r"((b)[1]))
// f16-accumulate variant: C/D are 2x f16x2 regs — 2x HMMA rate
#define MMA_F16A(c, a, b) \
    asm volatile("mma.sync.aligned.m16n8k16.row.col.f16.f16.f16.f16 " \
        "{%0,%1},{%2,%3,%4,%5},{%6,%7},{%0,%1};" \
        : "+r"((c)[0]), "+r"((c)[1]) \
        : "r"((a)[0]), "r"((a)[1]), "r"((a)[2]), "r"((a)[3]), "r"((b)[0]), "r"((b)[1]))
#define CP16(dst, src) \
    asm volatile("cp.async.cg.shared.global [%0], [%1], 16;" :: "r"(dst), "l"(src))
#define CP_COMMIT asm volatile("cp.async.commit_group;")
#define CP_WAIT(n) asm volatile("cp.async.wait_group %0;" :: "n"(n))
__device__ __forceinline__ uint32_t exp2_f16x2(float lo, float hi) {
    uint32_t d;
    asm("{.reg .b32 t;\n\t"
        "cvt.rn.f16x2.f32 t, %1, %2;\n\t"
        "ex2.approx.f16x2 %0, t;}"
        : "=r"(d) : "f"(hi), "f"(lo));
    return d;
}

// ---------------- fp32 -> f16 weight convert ---------------------------------
__global__ void __launch_bounds__(256) convert_f16(const float* __restrict__ in,
                                                   __half* __restrict__ outw) {
    int i = blockIdx.x * 256 + threadIdx.x;
    float4 v = ((const float4*)in)[i];
    __half2 h0 = __floats2half2_rn(v.x, v.y);
    __half2 h1 = __floats2half2_rn(v.z, v.w);
    uint2 w;
    w.x = *(uint32_t*)&h0;
    w.y = *(uint32_t*)&h1;
    ((uint2*)outw)[i] = w;
}

// ---------------- pipelined f16 GEMM (f16 accumulate, k-chunk 64, 3-stage) ---
// C = A(f16)[M,K] @ W(f16)[K,N] + bias (+ residual Res).
// qkvmode: Q cols (col%192<64) bf16*log2e/8, K cols bf16, V cols f16.
#define AST 72
#define BST 136
#define A_EL (128*AST)
#define B_EL (64*BST)
#define GSMEM ((3*A_EL + 3*B_EL) * 2)
__global__ void __launch_bounds__(256, 2) gemm_f16(
    const __half* __restrict__ A, const __half* __restrict__ W,
    const float* __restrict__ bias, const float* __restrict__ Res,
    float* __restrict__ Cf, __nv_bfloat16* __restrict__ Cb, int N, int K,
    int qkvmode) {
    extern __shared__ __align__(16) uint16_t sm_[];
    uint16_t* sA = sm_;
    uint16_t* sB = sm_ + 3 * A_EL;
    const int tid = threadIdx.x;
    const int lane = tid & 31, warp = tid >> 5;
    const int wr = warp >> 2, wc = warp & 3;
    const size_t aRow0 = (size_t)blockIdx.y * 128;
    const int bCol0 = blockIdx.x * 128;
    const int lrow = lane & 15, lseg = lane >> 4;

    uint32_t acc[16][2];               // f16x2 accumulators
    #pragma unroll
    for (int i = 0; i < 16; i++) { acc[i][0] = 0u; acc[i][1] = 0u; }

    const int nk = K / 64;
    auto load_stage = [&](int st, int kt) {
        #pragma unroll
        for (int i = 0; i < 4; i++) {
            int c = tid + i * 256;
            int r = c >> 3, seg = c & 7;
            CP16(s2u(&sA[st * A_EL + r * AST + seg * 8]),
                 A + (aRow0 + r) * K + kt + seg * 8);
        }
        #pragma unroll
        for (int i = 0; i < 4; i++) {
            int c = tid + i * 256;
            int r = c >> 4, seg = c & 15;
            CP16(s2u(&sB[st * B_EL + r * BST + seg * 8]),
                 W + (size_t)(kt + r) * N + bCol0 + seg * 8);
        }
    };
    load_stage(0, 0); CP_COMMIT;
    load_stage(1, 64); CP_COMMIT;

    int stC = 0, stL = 2;
    for (int it = 0; it < nk; it++) {
        if (it == nk - 1) { CP_WAIT(0); } else { CP_WAIT(1); }
        __syncthreads();
        if (it + 2 < nk) { load_stage(stL, (it + 2) * 64); CP_COMMIT; }
        if (++stL == 3) stL = 0;
        #pragma unroll
        for (int k16 = 0; k16 < 64; k16 += 16) {
            uint32_t a[4][4], bf[4][2];
            #pragma unroll
            for (int mi = 0; mi < 4; mi++)
                LDSM4(a[mi], s2u(&sA[stC * A_EL + (wr * 64 + mi * 16 + lrow) * AST + k16 + lseg * 8]));
            #pragma unroll
            for (int np = 0; np < 2; np++) {
                uint32_t t4[4];
                LDSM4T(t4, s2u(&sB[stC * B_EL + (k16 + lrow) * BST + wc * 32 + np * 16 + lseg * 8]));
                bf[np*2][0] = t4[0]; bf[np*2][1] = t4[1];
                bf[np*2+1][0] = t4[2]; bf[np*2+1][1] = t4[3];
            }
            #pragma unroll
            for (int mi = 0; mi < 4; mi++)
                #pragma unroll
                for (int ni = 0; ni < 4; ni++)
                    MMA_F16A(acc[mi * 4 + ni], a[mi], bf[ni]);
        }
        if (++stC == 3) stC = 0;
    }
    #pragma unroll
    for (int mi = 0; mi < 4; mi++) {
        size_t row = aRow0 + wr * 64 + mi * 16 + (lane >> 2);
        #pragma unroll
        for (int ni = 0; ni < 4; ni++) {
            int col = bCol0 + wc * 32 + ni * 8 + (lane & 3) * 2;
            float b0 = 0.f, b1 = 0.f;
            if (bias) { b0 = bias[col]; b1 = bias[col + 1]; }
            __half2 h0 = *(__half2*)&acc[mi * 4 + ni][0];
            __half2 h1 = *(__half2*)&acc[mi * 4 + ni][1];
            float v00 = __low2float(h0) + b0, v01 = __high2float(h0) + b1;
            float v10 = __low2float(h1) + b0, v11 = __high2float(h1) + b1;
            if (Res) {
                float2 r0 = *(const float2*)&Res[row * N + col];
                float2 r1 = *(const float2*)&Res[(row + 8) * N + col];
                v00 += r0.x; v01 += r0.y;
                v10 += r1.x; v11 += r1.y;
            }
            if (Cf) {
                *(float2*)&Cf[row * N + col] = make_float2(v00, v01);
                *(float2*)&Cf[(row + 8) * N + col] = make_float2(v10, v11);
            }
            if (Cb) {
                uint32_t w0, w1;
                int cm = col % 192;
                if (qkvmode && cm >= 128) {           // V: f16 bits
                    __half2 q0 = __floats2half2_rn(v00, v01);
                    __half2 q1 = __floats2half2_rn(v10, v11);
                    w0 = *(uint32_t*)&q0; w1 = *(uint32_t*)&q1;
                } else {
                    float sc = (qkvmode && cm < 64) ? 0.1803368801f : 1.0f;
                    __nv_bfloat162 t0 = __floats2bfloat162_rn(v00 * sc, v01 * sc);
                    __nv_bfloat162 t1 = __floats2bfloat162_rn(v10 * sc, v11 * sc);
                    w0 = *(uint32_t*)&t0; w1 = *(uint32_t*)&t1;
                }
                *(uint32_t*)&Cb[row * N + col] = w0;
                *(uint32_t*)&Cb[(row + 8) * N + col] = w1;
            }
        }
    }
}

// ---------------- fused flash attention (f16 exp + mma row-sums) -------------
#define KST 72
#define FSMEM ((128*KST + 3*64*KST*2) * 2)   // 73728 bytes
__global__ void __launch_bounds__(256) flash_kernel(
    const __nv_bfloat16* __restrict__ qkvb, __half* __restrict__ ob) {
    extern __shared__ __align__(16) __nv_bfloat16 fsm_[];
    __nv_bfloat16* sQ = fsm_;
    __nv_bfloat16* sK = fsm_ + 128 * KST;
    __nv_bfloat16* sV = sK + 3 * 64 * KST;
    const int bh = blockIdx.y;
    const int b = bh >> 3, h = bh & 7;
    const int q0 = blockIdx.x * 128;
    const int tid = threadIdx.x, lane = tid & 31, warp = tid >> 5;
    const __nv_bfloat16* qb = qkvb + (size_t)(b * S_) * 1536 + h * 192;
    const __nv_bfloat16* kb = qb + 64;
    const __nv_bfloat16* vb = qb + 128;

    auto load_kv = [&](int buf, int t) {
        #pragma unroll
        for (int i = 0; i < 2; i++) {
            int c = tid + i * 256;
            int r = c >> 3, seg = c & 7;
            CP16(s2u(&sK[buf * 64 * KST + r * KST + seg * 8]),
                 kb + (size_t)(t * 64 + r) * 1536 + seg * 8);
            CP16(s2u(&sV[buf * 64 * KST + r * KST + seg * 8]),
                 vb + (size_t)(t * 64 + r) * 1536 + seg * 8);
        }
    };
    #pragma unroll
    for (int i = 0; i < 4; i++) {
        int c = tid + i * 256;
        int r = c >> 3, seg = c & 7;
        CP16(s2u(&sQ[r * KST + seg * 8]), qb + (size_t)(q0 + r) * 1536 + seg * 8);
    }
    load_kv(0, 0); CP_COMMIT;
    load_kv(1, 1); CP_COMMIT;
    CP_WAIT(1);
    __syncthreads();

    uint32_t qf[4][4];
    const int qr = warp * 16;
    #pragma unroll
    for (int kk = 0; kk < 4; kk++)
        LDSM4(qf[kk], s2u(&sQ[(qr + (lane & 15)) * KST + kk * 16 + (lane >> 4) * 8]));

    float o[8][4];
    #pragma unroll
    for (int i = 0; i < 8; i++)
        #pragma unroll
        for (int j = 0; j < 4; j++) o[i][j] = 0.f;
    float lacc[4] = {0.f, 0.f, 0.f, 0.f};
    const uint32_t onesb[2] = {0x3C003C00u, 0x3C003C00u};

    const int kRow = ((lane >> 4) & 1) * 8 + (lane & 7);
    const int kCol = ((lane >> 3) & 1) * 8;
    const int vRow = ((lane >> 3) & 1) * 8 + (lane & 7);
    const int vCol = ((lane >> 4) & 1) * 8;

    int stC = 0, stL = 2;
    for (int t = 0; t < 16; t++) {
        if (t == 15) { CP_WAIT(0); } else { CP_WAIT(1); }
        __syncthreads();
        if (t + 2 < 16) { load_kv(stL, t + 2); CP_COMMIT; }
        if (++stL == 3) stL = 0;
        const int kbuf = stC * 64 * KST;
        if (++stC == 3) stC = 0;

        float s[8][4];
        #pragma unroll
        for (int i = 0; i < 8; i++)
            #pragma unroll
            for (int j = 0; j < 4; j++) s[i][j] = 0.f;
        #pragma unroll
        for (int kk = 0; kk < 4; kk++) {
            uint32_t kf[8][2];
            #pragma unroll
            for (int nf2 = 0; nf2 < 4; nf2++) {
                uint32_t t4[4];
                LDSM4(t4, s2u(&sK[kbuf + (nf2 * 16 + kRow) * KST + kk * 16 + kCol]));
                kf[nf2*2][0] = t4[0]; kf[nf2*2][1] = t4[1];
                kf[nf2*2+1][0] = t4[2]; kf[nf2*2+1][1] = t4[3];
            }
            #pragma unroll
            for (int nf = 0; nf < 8; nf++)
                MMA_BF16(s[nf], qf[kk], kf[nf]);
        }

        uint32_t pa[4][4];
        #pragma unroll
        for (int kk = 0; kk < 4; kk++) {
            pa[kk][0] = exp2_f16x2(s[2*kk][0],   s[2*kk][1]);
            pa[kk][1] = exp2_f16x2(s[2*kk][2],   s[2*kk][3]);
            pa[kk][2] = exp2_f16x2(s[2*kk+1][0], s[2*kk+1][1]);
            pa[kk][3] = exp2_f16x2(s[2*kk+1][2], s[2*kk+1][3]);
            MMA_F16(lacc, pa[kk], onesb);
        }

        #pragma unroll
        for (int kk = 0; kk < 4; kk++) {
            uint32_t vf[8][2];
            #pragma unroll
            for (int nf2 = 0; nf2 < 4; nf2++) {
                uint32_t t4[4];
                LDSM4T(t4, s2u(&sV[kbuf + (kk * 16 + vRow) * KST + nf2 * 16 + vCol]));
                vf[nf2*2][0] = t4[0]; vf[nf2*2][1] = t4[1];
                vf[nf2*2+1][0] = t4[2]; vf[nf2*2+1][1] = t4[3];
            }
            #pragma unroll
            for (int nf = 0; nf < 8; nf++)
                MMA_F16(o[nf], pa[kk], vf[nf]);
        }
    }

    float inv0 = 1.f / lacc[0], inv1 = 1.f / lacc[2];
    size_t r0 = (size_t)b * S_ + q0 + qr + (lane >> 2);
    size_t r1 = r0 + 8;
    #pragma unroll
    for (int nf = 0; nf < 8; nf++) {
        int col = h * 64 + nf * 8 + (lane & 3) * 2;
        *(__half2*)&ob[r0 * D_ + col] =
            __floats2half2_rn(o[nf][0] * inv0, o[nf][1] * inv0);
        *(__half2*)&ob[r1 * D_ + col] =
            __floats2half2_rn(o[nf][2] * inv1, o[nf][3] * inv1);
    }
}

// ---------------- embedding + sinusoidal PE ----------------------------------
__global__ void __launch_bounds__(256) embed_kernel(const int* __restrict__ tokens,
                                                    const float* __restrict__ emb) {
    int idx = blockIdx.x * 256 + threadIdx.x;
    int d = idx & (D_ - 1);
    int bs = idx >> 9;
    int s = bs & (S_ - 1);
    int tok = tokens[bs];
    float div = expf((float)(d & ~1) * (-9.210340371976184f / (float)D_));
    float ang = (float)s * div;
    float pe = (d & 1) ? cosf(ang) : sinf(ang);
    float v = emb[(size_t)tok * D_ + d] + pe;
    g_x[idx] = v;
    g_xb[idx] = __float2half(v);
}

// ---------------- LayerNorm (input y pre-summed: proj+bias+residual) ---------
__global__ void __launch_bounds__(128) ln_kernel(const float* __restrict__ gamma,
                                                 const float* __restrict__ beta) {
    size_t r = blockIdx.x;
    int tid = threadIdx.x;
    float4 y = *(float4*)(g_p + r * D_ + tid * 4);
    __shared__ float sm[4], ss[4];
    float s = y.x + y.y + y.z + y.w;
    #pragma unroll
    for (int o2 = 16; o2; o2 >>= 1) s += __shfl_xor_sync(0xffffffffu, s, o2);
    if ((tid & 31) == 0) sm[tid >> 5] = s;
    __syncthreads();
    float mean = (sm[0] + sm[1] + sm[2] + sm[3]) * (1.0f / D_);
    float dx = y.x - mean, dy = y.y - mean, dz = y.z - mean, dw = y.w - mean;
    float sq = dx*dx + dy*dy + dz*dz + dw*dw;
    #pragma unroll
    for (int o2 = 16; o2; o2 >>= 1) sq += __shfl_xor_sync(0xffffffffu, sq, o2);
    if ((tid & 31) == 0) ss[tid >> 5] = sq;
    __syncthreads();
    float var = (ss[0] + ss[1] + ss[2] + ss[3]) * (1.0f / D_);
    float inv = rsqrtf(var + 1e-5f);
    float4 g = *(const float4*)(gamma + tid * 4);
    float4 be = *(const float4*)(beta + tid * 4);
    float4 out;
    out.x = dx * inv * g.x + be.x; out.y = dy * inv * g.y + be.y;
    out.z = dz * inv * g.z + be.z; out.w = dw * inv * g.w + be.w;
    *(float4*)(g_x + r * D_ + tid * 4) = out;
    *(__half2*)&g_xb[r * D_ + tid * 4]     = __floats2half2_rn(out.x, out.y);
    *(__half2*)&g_xb[r * D_ + tid * 4 + 2] = __floats2half2_rn(out.z, out.w);
}

// ---------------- mean pool / MLP ---------------------------------------------
__global__ void __launch_bounds__(512) pool_kernel() {
    int b = blockIdx.x, d = threadIdx.x;
    const float* base = g_x + (size_t)b * S_ * D_ + d;
    float s = 0.f;
    for (int i = 0; i < S_; i++) s += base[(size_t)i * D_];
    g_pool[b * D_ + d] = s * (1.0f / S_);
}

__global__ void __launch_bounds__(256) mlp1_kernel(const float* __restrict__ w,
                                                   const float* __restrict__ bias) {
    int f = blockIdx.x * 256 + threadIdx.x;
    int b = blockIdx.y;
    float acc = bias[f];
    const float* pr = g_pool + b * D_;
    for (int d = 0; d < D_; d++) acc = fmaf(pr[d], w[(size_t)d * FF_ + f], acc);
    g_h1[b * FF_ + f] = fmaxf(acc, 0.f);
}

__global__ void __launch_bounds__(192) mlp2_kernel(const float* __restrict__ w,
                                                   const float* __restrict__ bias,
                                                   float* __restrict__ out) {
    int t = threadIdx.x;
    int b = t / C_, c = t % C_;
    float acc = bias[c];
    const float* hr = g_h1 + b * FF_;
    for (int f = 0; f < FF_; f++) acc = fmaf(hr[f], w[f * C_ + c], acc);
    out[b * C_ + c] = acc;
}

// ---------------- launch ------------------------------------------------------
extern "C" void kernel_launch(void* const* d_in, const int* in_sizes, int n_in,
                              void* d_out, int out_size) {
    const int*   tokens = (const int*)d_in[0];
    const float* emb    = (const float*)d_in[1];
    const float* qkv_w  = (const float*)d_in[2];
    const float* qkv_b  = (const float*)d_in[3];
    const float* fc_w   = (const float*)d_in[4];
    const float* fc_b   = (const float*)d_in[5];
    const float* gamma  = (const float*)d_in[6];
    const float* beta   = (const float*)d_in[7];
    const float* fc1_w  = (const float*)d_in[8];
    const float* fc1_b  = (const float*)d_in[9];
    const float* fc2_w  = (const float*)d_in[10];
    const float* fc2_b  = (const float*)d_in[11];
    float* out = (float*)d_out;
    (void)in_sizes; (void)n_in; (void)out_size;

    cudaFuncSetAttribute(gemm_f16, cudaFuncAttributeMaxDynamicSharedMemorySize, GSMEM);
    cudaFuncSetAttribute(flash_kernel, cudaFuncAttributeMaxDynamicSharedMemorySize, FSMEM);

    __half *xb, *obf, *wf;
    __nv_bfloat16 *qkvb;
    float *x, *p;
    cudaGetSymbolAddress((void**)&x,    g_x);
    cudaGetSymbolAddress((void**)&xb,   g_xb);
    cudaGetSymbolAddress((void**)&qkvb, g_qkvb);
    cudaGetSymbolAddress((void**)&obf,  g_ob);
    cudaGetSymbolAddress((void**)&p,    g_p);
    cudaGetSymbolAddress((void**)&wf,   g_wf);

    embed_kernel<<<(BS_ * D_) / 256, 256>>>(tokens, emb);
    for (int l = 0; l < L_; l++) {
        convert_f16<<<(D_ * 3 * D_) / 1024, 256>>>(
            qkv_w + (size_t)l * D_ * 3 * D_, wf + WQKV_OFF(l));
        convert_f16<<<(D_ * D_) / 1024, 256>>>(
            fc_w + (size_t)l * D_ * D_, wf + WFC_OFF(l));
    }

    for (int l = 0; l < L_; l++) {
        gemm_f16<<<dim3(3 * D_ / 128, BS_ / 128), 256, GSMEM>>>(
            xb, wf + WQKV_OFF(l), qkv_b + (size_t)l * 3 * D_, (const float*)nullptr,
            (float*)nullptr, qkvb, 3 * D_, D_, 1);
        flash_kernel<<<dim3(S_ / 128, B_ * H_), 256, FSMEM>>>(qkvb, obf);
        gemm_f16<<<dim3(D_ / 128, BS_ / 128), 256, GSMEM>>>(
            obf, wf + WFC_OFF(l), fc_b + (size_t)l * D_, x,
            p, (__nv_bfloat16*)nullptr, D_, D_, 0);
        ln_kernel<<<BS_, 128>>>(gamma, beta);
    }

    pool_kernel<<<B_, 512>>>();
    mlp1_kernel<<<dim3(FF_ / 256, B_), 256>>>(fc1_w, fc1_b);
    mlp2_kernel<<<1, B_ * C_>>>(fc2_w, fc2_b, out);
}

// round 17
// speedup vs baseline: 1.4446x; 1.0278x over previous
#include <cuda_runtime.h>
#include <cuda_bf16.h>
#include <cuda_fp16.h>
#include <math.h>
#include <stdint.h>

#define B_ 32
#define S_ 1024
#define D_ 512
#define H_ 8
#define L_ 3
#define FF_ 2048
#define C_ 6
#define BS_ (B_*S_)

// ---------------- scratch (device globals) ----------------------------------
static __device__ float          g_x[(size_t)BS_*D_];        // residual fp32
static __device__ __half         g_xb[(size_t)BS_*D_];       // residual f16
static __device__ __nv_bfloat16  g_qkvb[(size_t)BS_*3*D_];   // Q(bf16,scaled) K(bf16) V(f16 bits)
static __device__ __half         g_ob[(size_t)BS_*D_];       // attn out f16
static __device__ float          g_p[(size_t)BS_*D_];        // proj+bias+residual fp32
static __device__ float          g_pool[B_*D_];
static __device__ float          g_h1[B_*FF_];
#define WQKV_OFF(l) ((size_t)(l) * (size_t)(D_*3*D_))
#define WFC_OFF(l)  ((size_t)3 * (D_*3*D_) + (size_t)(l) * (D_*D_))
#define WTOT ((size_t)3 * (D_*3*D_) + (size_t)3 * (D_*D_))
static __device__ __half         g_wf[WTOT];                 // weights f16

// ---------------- asm helpers ------------------------------------------------
__device__ __forceinline__ uint32_t s2u(const void* p) {
    return (uint32_t)__cvta_generic_to_shared(p);
}
#define LDSM4(R, addr) \
    asm volatile("ldmatrix.sync.aligned.m8n8.x4.shared.b16 {%0,%1,%2,%3}, [%4];" \
        : "=r"((R)[0]), "=r"((R)[1]), "=r"((R)[2]), "=r"((R)[3]) : "r"(addr))
#define LDSM4T(R, addr) \
    asm volatile("ldmatrix.sync.aligned.m8n8.x4.trans.shared.b16 {%0,%1,%2,%3}, [%4];" \
        : "=r"((R)[0]), "=r"((R)[1]), "=r"((R)[2]), "=r"((R)[3]) : "r"(addr))
#define MMA_BF16(c, a, b) \
    asm volatile("mma.sync.aligned.m16n8k16.row.col.f32.bf16.bf16.f32 " \
        "{%0,%1,%2,%3},{%4,%5,%6,%7},{%8,%9},{%0,%1,%2,%3};" \
        : "+f"((c)[0]), "+f"((c)[1]), "+f"((c)[2]), "+f"((c)[3]) \
        : "r"((a)[0]), "r"((a)[1]), "r"((a)[2]), "r"((a)[3]), "r"((b)[0]), "r"((b)[1]))
#define MMA_F16(c, a, b) \
    asm volatile("mma.sync.aligned.m16n8k16.row.col.f32.f16.f16.f32 " \
        "{%0,%1,%2,%3},{%4,%5,%6,%7},{%8,%9},{%0,%1,%2,%3};" \
        : "+f"((c)[0]), "+f"((c)[1]), "+f"((c)[2]), "+f"((c)[3]) \
        : "r"((a)[0]), "r"((a)[1]), "r"((a)[2]), "r"((a)[3]), "r"((b)[0]), "r"((b)[1]))
// f16-accumulate variant: C/D are 2x f16x2 regs
#define MMA_F16A(c, a, b) \
    asm volatile("mma.sync.aligned.m16n8k16.row.col.f16.f16.f16.f16 " \
        "{%0,%1},{%2,%3,%4,%5},{%6,%7},{%0,%1};" \
        : "+r"((c)[0]), "+r"((c)[1]) \
        : "r"((a)[0]), "r"((a)[1]), "r"((a)[2]), "r"((a)[3]), "r"((b)[0]), "r"((b)[1]))
#define CP16(dst, src) \
    asm volatile("cp.async.cg.shared.global [%0], [%1], 16;" :: "r"(dst), "l"(src))
#define CP_COMMIT asm volatile("cp.async.commit_group;")
#define CP_WAIT(n) asm volatile("cp.async.wait_group %0;" :: "n"(n))
__device__ __forceinline__ uint32_t exp2_f16x2(float lo, float hi) {
    uint32_t d;
    asm("{.reg .b32 t;\n\t"
        "cvt.rn.f16x2.f32 t, %1, %2;\n\t"
        "ex2.approx.f16x2 %0, t;}"
        : "=r"(d) : "f"(hi), "f"(lo));
    return d;
}

// ---------------- fp32 -> f16 weight convert ---------------------------------
__global__ void __launch_bounds__(256) convert_f16(const float* __restrict__ in,
                                                   __half* __restrict__ outw) {
    int i = blockIdx.x * 256 + threadIdx.x;
    float4 v = ((const float4*)in)[i];
    __half2 h0 = __floats2half2_rn(v.x, v.y);
    __half2 h1 = __floats2half2_rn(v.z, v.w);
    uint2 w;
    w.x = *(uint32_t*)&h0;
    w.y = *(uint32_t*)&h1;
    ((uint2*)outw)[i] = w;
}

// ---------------- pipelined f16 GEMM (f16 acc, k-chunk 64, 2-stage, 3 CTA/SM)
// C = A(f16)[M,K] @ W(f16)[K,N] + bias (+ residual Res).
// qkvmode: Q cols (col%192<64) bf16*log2e/8, K cols bf16, V cols f16.
#define AST 72
#define BST 136
#define A_EL (128*AST)
#define B_EL (64*BST)
#define GSMEM ((2*A_EL + 2*B_EL) * 2)   // 71680 bytes -> 3 CTAs/SM
__global__ void __launch_bounds__(256, 3) gemm_f16(
    const __half* __restrict__ A, const __half* __restrict__ W,
    const float* __restrict__ bias, const float* __restrict__ Res,
    float* __restrict__ Cf, __nv_bfloat16* __restrict__ Cb, int N, int K,
    int qkvmode) {
    extern __shared__ __align__(16) uint16_t sm_[];
    uint16_t* sA = sm_;                   // 2 x A_EL
    uint16_t* sB = sm_ + 2 * A_EL;        // 2 x B_EL
    const int tid = threadIdx.x;
    const int lane = tid & 31, warp = tid >> 5;
    const int wr = warp >> 2, wc = warp & 3;
    const size_t aRow0 = (size_t)blockIdx.y * 128;
    const int bCol0 = blockIdx.x * 128;
    const int lrow = lane & 15, lseg = lane >> 4;

    uint32_t acc[16][2];               // f16x2 accumulators
    #pragma unroll
    for (int i = 0; i < 16; i++) { acc[i][0] = 0u; acc[i][1] = 0u; }

    const int nk = K / 64;
    auto load_stage = [&](int st, int kt) {
        #pragma unroll
        for (int i = 0; i < 4; i++) {
            int c = tid + i * 256;
            int r = c >> 3, seg = c & 7;
            CP16(s2u(&sA[st * A_EL + r * AST + seg * 8]),
                 A + (aRow0 + r) * K + kt + seg * 8);
        }
        #pragma unroll
        for (int i = 0; i < 4; i++) {
            int c = tid + i * 256;
            int r = c >> 4, seg = c & 15;
            CP16(s2u(&sB[st * B_EL + r * BST + seg * 8]),
                 W + (size_t)(kt + r) * N + bCol0 + seg * 8);
        }
    };
    load_stage(0, 0); CP_COMMIT;
    load_stage(1, 64); CP_COMMIT;

    for (int it = 0; it < nk; it++) {
        int stC = it & 1;
        if (it == nk - 1) { CP_WAIT(0); } else { CP_WAIT(1); }
        __syncthreads();
        #pragma unroll
        for (int k16 = 0; k16 < 64; k16 += 16) {
            uint32_t a[4][4], bf[4][2];
            #pragma unroll
            for (int mi = 0; mi < 4; mi++)
                LDSM4(a[mi], s2u(&sA[stC * A_EL + (wr * 64 + mi * 16 + lrow) * AST + k16 + lseg * 8]));
            #pragma unroll
            for (int np = 0; np < 2; np++) {
                uint32_t t4[4];
                LDSM4T(t4, s2u(&sB[stC * B_EL + (k16 + lrow) * BST + wc * 32 + np * 16 + lseg * 8]));
                bf[np*2][0] = t4[0]; bf[np*2][1] = t4[1];
                bf[np*2+1][0] = t4[2]; bf[np*2+1][1] = t4[3];
            }
            #pragma unroll
            for (int mi = 0; mi < 4; mi++)
                #pragma unroll
                for (int ni = 0; ni < 4; ni++)
                    MMA_F16A(acc[mi * 4 + ni], a[mi], bf[ni]);
        }
        // stage reuse barrier, then prefetch next+1 into the buffer just consumed
        if (it + 2 < nk) {
            __syncthreads();
            load_stage(stC, (it + 2) * 64); CP_COMMIT;
        }
    }
    #pragma unroll
    for (int mi = 0; mi < 4; mi++) {
        size_t row = aRow0 + wr * 64 + mi * 16 + (lane >> 2);
        #pragma unroll
        for (int ni = 0; ni < 4; ni++) {
            int col = bCol0 + wc * 32 + ni * 8 + (lane & 3) * 2;
            float b0 = 0.f, b1 = 0.f;
            if (bias) { b0 = bias[col]; b1 = bias[col + 1]; }
            __half2 h0 = *(__half2*)&acc[mi * 4 + ni][0];
            __half2 h1 = *(__half2*)&acc[mi * 4 + ni][1];
            float v00 = __low2float(h0) + b0, v01 = __high2float(h0) + b1;
            float v10 = __low2float(h1) + b0, v11 = __high2float(h1) + b1;
            if (Res) {
                float2 r0 = *(const float2*)&Res[row * N + col];
                float2 r1 = *(const float2*)&Res[(row + 8) * N + col];
                v00 += r0.x; v01 += r0.y;
                v10 += r1.x; v11 += r1.y;
            }
            if (Cf) {
                *(float2*)&Cf[row * N + col] = make_float2(v00, v01);
                *(float2*)&Cf[(row + 8) * N + col] = make_float2(v10, v11);
            }
            if (Cb) {
                uint32_t w0, w1;
                int cm = col % 192;
                if (qkvmode && cm >= 128) {           // V: f16 bits
                    __half2 q0 = __floats2half2_rn(v00, v01);
                    __half2 q1 = __floats2half2_rn(v10, v11);
                    w0 = *(uint32_t*)&q0; w1 = *(uint32_t*)&q1;
                } else {
                    float sc = (qkvmode && cm < 64) ? 0.1803368801f : 1.0f;
                    __nv_bfloat162 t0 = __floats2bfloat162_rn(v00 * sc, v01 * sc);
                    __nv_bfloat162 t1 = __floats2bfloat162_rn(v10 * sc, v11 * sc);
                    w0 = *(uint32_t*)&t0; w1 = *(uint32_t*)&t1;
                }
                *(uint32_t*)&Cb[row * N + col] = w0;
                *(uint32_t*)&Cb[(row + 8) * N + col] = w1;
            }
        }
    }
}

// ---------------- fused flash attention (f16 exp + mma row-sums) -------------
#define KST 72
#define FSMEM ((128*KST + 3*64*KST*2) * 2)   // 73728 bytes
__global__ void __launch_bounds__(256) flash_kernel(
    const __nv_bfloat16* __restrict__ qkvb, __half* __restrict__ ob) {
    extern __shared__ __align__(16) __nv_bfloat16 fsm_[];
    __nv_bfloat16* sQ = fsm_;
    __nv_bfloat16* sK = fsm_ + 128 * KST;
    __nv_bfloat16* sV = sK + 3 * 64 * KST;
    const int bh = blockIdx.y;
    const int b = bh >> 3, h = bh & 7;
    const int q0 = blockIdx.x * 128;
    const int tid = threadIdx.x, lane = tid & 31, warp = tid >> 5;
    const __nv_bfloat16* qb = qkvb + (size_t)(b * S_) * 1536 + h * 192;
    const __nv_bfloat16* kb = qb + 64;
    const __nv_bfloat16* vb = qb + 128;

    auto load_kv = [&](int buf, int t) {
        #pragma unroll
        for (int i = 0; i < 2; i++) {
            int c = tid + i * 256;
            int r = c >> 3, seg = c & 7;
            CP16(s2u(&sK[buf * 64 * KST + r * KST + seg * 8]),
                 kb + (size_t)(t * 64 + r) * 1536 + seg * 8);
            CP16(s2u(&sV[buf * 64 * KST + r * KST + seg * 8]),
                 vb + (size_t)(t * 64 + r) * 1536 + seg * 8);
        }
    };
    #pragma unroll
    for (int i = 0; i < 4; i++) {
        int c = tid + i * 256;
        int r = c >> 3, seg = c & 7;
        CP16(s2u(&sQ[r * KST + seg * 8]), qb + (size_t)(q0 + r) * 1536 + seg * 8);
    }
    load_kv(0, 0); CP_COMMIT;
    load_kv(1, 1); CP_COMMIT;
    CP_WAIT(1);
    __syncthreads();

    uint32_t qf[4][4];
    const int qr = warp * 16;
    #pragma unroll
    for (int kk = 0; kk < 4; kk++)
        LDSM4(qf[kk], s2u(&sQ[(qr + (lane & 15)) * KST + kk * 16 + (lane >> 4) * 8]));

    float o[8][4];
    #pragma unroll
    for (int i = 0; i < 8; i++)
        #pragma unroll
        for (int j = 0; j < 4; j++) o[i][j] = 0.f;
    float lacc[4] = {0.f, 0.f, 0.f, 0.f};
    const uint32_t onesb[2] = {0x3C003C00u, 0x3C003C00u};

    const int kRow = ((lane >> 4) & 1) * 8 + (lane & 7);
    const int kCol = ((lane >> 3) & 1) * 8;
    const int vRow = ((lane >> 3) & 1) * 8 + (lane & 7);
    const int vCol = ((lane >> 4) & 1) * 8;

    int stC = 0, stL = 2;
    for (int t = 0; t < 16; t++) {
        if (t == 15) { CP_WAIT(0); } else { CP_WAIT(1); }
        __syncthreads();
        if (t + 2 < 16) { load_kv(stL, t + 2); CP_COMMIT; }
        if (++stL == 3) stL = 0;
        const int kbuf = stC * 64 * KST;
        if (++stC == 3) stC = 0;

        float s[8][4];
        #pragma unroll
        for (int i = 0; i < 8; i++)
            #pragma unroll
            for (int j = 0; j < 4; j++) s[i][j] = 0.f;
        #pragma unroll
        for (int kk = 0; kk < 4; kk++) {
            uint32_t kf[8][2];
            #pragma unroll
            for (int nf2 = 0; nf2 < 4; nf2++) {
                uint32_t t4[4];
                LDSM4(t4, s2u(&sK[kbuf + (nf2 * 16 + kRow) * KST + kk * 16 + kCol]));
                kf[nf2*2][0] = t4[0]; kf[nf2*2][1] = t4[1];
                kf[nf2*2+1][0] = t4[2]; kf[nf2*2+1][1] = t4[3];
            }
            #pragma unroll
            for (int nf = 0; nf < 8; nf++)
                MMA_BF16(s[nf], qf[kk], kf[nf]);
        }

        uint32_t pa[4][4];
        #pragma unroll
        for (int kk = 0; kk < 4; kk++) {
            pa[kk][0] = exp2_f16x2(s[2*kk][0],   s[2*kk][1]);
            pa[kk][1] = exp2_f16x2(s[2*kk][2],   s[2*kk][3]);
            pa[kk][2] = exp2_f16x2(s[2*kk+1][0], s[2*kk+1][1]);
            pa[kk][3] = exp2_f16x2(s[2*kk+1][2], s[2*kk+1][3]);
            MMA_F16(lacc, pa[kk], onesb);
        }

        #pragma unroll
        for (int kk = 0; kk < 4; kk++) {
            uint32_t vf[8][2];
            #pragma unroll
            for (int nf2 = 0; nf2 < 4; nf2++) {
                uint32_t t4[4];
                LDSM4T(t4, s2u(&sV[kbuf + (kk * 16 + vRow) * KST + nf2 * 16 + vCol]));
                vf[nf2*2][0] = t4[0]; vf[nf2*2][1] = t4[1];
                vf[nf2*2+1][0] = t4[2]; vf[nf2*2+1][1] = t4[3];
            }
            #pragma unroll
            for (int nf = 0; nf < 8; nf++)
                MMA_F16(o[nf], pa[kk], vf[nf]);
        }
    }

    float inv0 = 1.f / lacc[0], inv1 = 1.f / lacc[2];
    size_t r0 = (size_t)b * S_ + q0 + qr + (lane >> 2);
    size_t r1 = r0 + 8;
    #pragma unroll
    for (int nf = 0; nf < 8; nf++) {
        int col = h * 64 + nf * 8 + (lane & 3) * 2;
        *(__half2*)&ob[r0 * D_ + col] =
            __floats2half2_rn(o[nf][0] * inv0, o[nf][1] * inv0);
        *(__half2*)&ob[r1 * D_ + col] =
            __floats2half2_rn(o[nf][2] * inv1, o[nf][3] * inv1);
    }
}

// ---------------- embedding + sinusoidal PE ----------------------------------
__global__ void __launch_bounds__(256) embed_kernel(const int* __restrict__ tokens,
                                                    const float* __restrict__ emb) {
    int idx = blockIdx.x * 256 + threadIdx.x;
    int d = idx & (D_ - 1);
    int bs = idx >> 9;
    int s = bs & (S_ - 1);
    int tok = tokens[bs];
    float div = expf((float)(d & ~1) * (-9.210340371976184f / (float)D_));
    float ang = (float)s * div;
    float pe = (d & 1) ? cosf(ang) : sinf(ang);
    float v = emb[(size_t)tok * D_ + d] + pe;
    g_x[idx] = v;
    g_xb[idx] = __float2half(v);
}

// ---------------- LayerNorm (input y pre-summed: proj+bias+residual) ---------
__global__ void __launch_bounds__(128) ln_kernel(const float* __restrict__ gamma,
                                                 const float* __restrict__ beta) {
    size_t r = blockIdx.x;
    int tid = threadIdx.x;
    float4 y = *(float4*)(g_p + r * D_ + tid * 4);
    __shared__ float sm[4], ss[4];
    float s = y.x + y.y + y.z + y.w;
    #pragma unroll
    for (int o2 = 16; o2; o2 >>= 1) s += __shfl_xor_sync(0xffffffffu, s, o2);
    if ((tid & 31) == 0) sm[tid >> 5] = s;
    __syncthreads();
    float mean = (sm[0] + sm[1] + sm[2] + sm[3]) * (1.0f / D_);
    float dx = y.x - mean, dy = y.y - mean, dz = y.z - mean, dw = y.w - mean;
    float sq = dx*dx + dy*dy + dz*dz + dw*dw;
    #pragma unroll
    for (int o2 = 16; o2; o2 >>= 1) sq += __shfl_xor_sync(0xffffffffu, sq, o2);
    if ((tid & 31) == 0) ss[tid >> 5] = sq;
    __syncthreads();
    float var = (ss[0] + ss[1] + ss[2] + ss[3]) * (1.0f / D_);
    float inv = rsqrtf(var + 1e-5f);
    float4 g = *(const float4*)(gamma + tid * 4);
    float4 be = *(const float4*)(beta + tid * 4);
    float4 out;
    out.x = dx * inv * g.x + be.x; out.y = dy * inv * g.y + be.y;
    out.z = dz * inv * g.z + be.z; out.w = dw * inv * g.w + be.w;
    *(float4*)(g_x + r * D_ + tid * 4) = out;
    *(__half2*)&g_xb[r * D_ + tid * 4]     = __floats2half2_rn(out.x, out.y);
    *(__half2*)&g_xb[r * D_ + tid * 4 + 2] = __floats2half2_rn(out.z, out.w);
}

// ---------------- mean pool / MLP ---------------------------------------------
__global__ void __launch_bounds__(512) pool_kernel() {
    int b = blockIdx.x, d = threadIdx.x;
    const float* base = g_x + (size_t)b * S_ * D_ + d;
    float s = 0.f;
    for (int i = 0; i < S_; i++) s += base[(size_t)i * D_];
    g_pool[b * D_ + d] = s * (1.0f / S_);
}

__global__ void __launch_bounds__(256) mlp1_kernel(const float* __restrict__ w,
                                                   const float* __restrict__ bias) {
    int f = blockIdx.x * 256 + threadIdx.x;
    int b = blockIdx.y;
    float acc = bias[f];
    const float* pr = g_pool + b * D_;
    for (int d = 0; d < D_; d++) acc = fmaf(pr[d], w[(size_t)d * FF_ + f], acc);
    g_h1[b * FF_ + f] = fmaxf(acc, 0.f);
}

__global__ void __launch_bounds__(192) mlp2_kernel(const float* __restrict__ w,
                                                   const float* __restrict__ bias,
                                                   float* __restrict__ out) {
    int t = threadIdx.x;
    int b = t / C_, c = t % C_;
    float acc = bias[c];
    const float* hr = g_h1 + b * FF_;
    for (int f = 0; f < FF_; f++) acc = fmaf(hr[f], w[f * C_ + c], acc);
    out[b * C_ + c] = acc;
}

// ---------------- launch ------------------------------------------------------
extern "C" void kernel_launch(void* const* d_in, const int* in_sizes, int n_in,
                              void* d_out, int out_size) {
    const int*   tokens = (const int*)d_in[0];
    const float* emb    = (const float*)d_in[1];
    const float* qkv_w  = (const float*)d_in[2];
    const float* qkv_b  = (const float*)d_in[3];
    const float* fc_w   = (const float*)d_in[4];
    const float* fc_b   = (const float*)d_in[5];
    const float* gamma  = (const float*)d_in[6];
    const float* beta   = (const float*)d_in[7];
    const float* fc1_w  = (const float*)d_in[8];
    const float* fc1_b  = (const float*)d_in[9];
    const float* fc2_w  = (const float*)d_in[10];
    const float* fc2_b  = (const float*)d_in[11];
    float* out = (float*)d_out;
    (void)in_sizes; (void)n_in; (void)out_size;

    cudaFuncSetAttribute(gemm_f16, cudaFuncAttributeMaxDynamicSharedMemorySize, GSMEM);
    cudaFuncSetAttribute(flash_kernel, cudaFuncAttributeMaxDynamicSharedMemorySize, FSMEM);

    __half *xb, *obf, *wf;
    __nv_bfloat16 *qkvb;
    float *x, *p;
    cudaGetSymbolAddress((void**)&x,    g_x);
    cudaGetSymbolAddress((void**)&xb,   g_xb);
    cudaGetSymbolAddress((void**)&qkvb, g_qkvb);
    cudaGetSymbolAddress((void**)&obf,  g_ob);
    cudaGetSymbolAddress((void**)&p,    g_p);
    cudaGetSymbolAddress((void**)&wf,   g_wf);

    embed_kernel<<<(BS_ * D_) / 256, 256>>>(tokens, emb);
    for (int l = 0; l < L_; l++) {
        convert_f16<<<(D_ * 3 * D_) / 1024, 256>>>(
            qkv_w + (size_t)l * D_ * 3 * D_, wf + WQKV_OFF(l));
        convert_f16<<<(D_ * D_) / 1024, 256>>>(
            fc_w + (size_t)l * D_ * D_, wf + WFC_OFF(l));
    }

    for (int l = 0; l < L_; l++) {
        gemm_f16<<<dim3(3 * D_ / 128, BS_ / 128), 256, GSMEM>>>(
            xb, wf + WQKV_OFF(l), qkv_b + (size_t)l * 3 * D_, (const float*)nullptr,
            (float*)nullptr, qkvb, 3 * D_, D_, 1);
        flash_kernel<<<dim3(S_ / 128, B_ * H_), 256, FSMEM>>>(qkvb, obf);
        gemm_f16<<<dim3(D_ / 128, BS_ / 128), 256, GSMEM>>>(
            obf, wf + WFC_OFF(l), fc_b + (size_t)l * D_, x,
            p, (__nv_bfloat16*)nullptr, D_, D_, 0);
        ln_kernel<<<BS_, 128>>>(gamma, beta);
    }

    pool_kernel<<<B_, 512>>>();
    mlp1_kernel<<<dim3(FF_ / 256, B_), 256>>>(fc1_w, fc1_b);
    mlp2_kernel<<<1, B_ * C_>>>(fc2_w, fc2_b, out);
}